// round 15
// baseline (speedup 1.0000x reference)
#include <cuda_runtime.h>
#include <cuda_bf16.h>
#include <cuda_fp16.h>
#include <cstdint>

// Problem constants (fixed by the dataset)
#define NN 100000
#define NE 1600000
#define SCAN_B 1024
#define NB_SCAN ((NN + SCAN_B - 1) / SCAN_B)   // 98
#define NTILES ((NN + 127) / 128)              // 782
#define MMA_GRID 148

// ---------------- scratch (device globals; no allocation allowed) -------------
__device__ int   g_flag64;           // 1 if edge_index buffer is int64
__device__ int   g_cnt[NN];
__device__ int   g_fill[NN];
__device__ int   g_ptr[NN + 1];
__device__ int   g_bsum[128];
__device__ int   g_csrc[NE];
__device__ float g_csw[NE];
__device__ float g_sumw[NN];
__device__ float g_loop[NN];
__device__ float g_xl[(size_t)NN * 128];   // aliased as half (all layers gather fp16)
__device__ float g_asrc[NN];
__device__ float g_adst[NN];
__device__ float g_asrc2[NN];
__device__ float g_adst2[NN];
__device__ float g_c[4];
__device__ __nv_bfloat16 g_bh[(size_t)NN * 128];
__device__ __nv_bfloat16 g_bl[(size_t)NN * 128];
__device__ __nv_bfloat16 g_wh[49152];
__device__ __nv_bfloat16 g_wl[49152];

// ---------------- helpers -------------------------------------------------------
__device__ __forceinline__ uint32_t s2u(const void* p) {
    uint32_t a;
    asm("{ .reg .u64 t; cvta.to.shared.u64 t, %1; cvt.u32.u64 %0, t; }"
        : "=r"(a) : "l"(p));
    return a;
}
__device__ __forceinline__ void cp16(uint32_t saddr, const void* g, int sz) {
    asm volatile("cp.async.cg.shared.global [%0], [%1], 16, %2;"
                 :: "r"(saddr), "l"(g), "r"(sz));
}
__device__ __forceinline__ void cp_commit() {
    asm volatile("cp.async.commit_group;" ::: "memory");
}
__device__ __forceinline__ void cp_wait1() {
    asm volatile("cp.async.wait_group 1;" ::: "memory");
}
__device__ __forceinline__ void cp_wait0() {
    asm volatile("cp.async.wait_group 0;" ::: "memory");
}
__device__ __forceinline__ void ldsm4(uint32_t* r, uint32_t addr) {
    asm volatile("ldmatrix.sync.aligned.m8n8.x4.shared.b16 {%0,%1,%2,%3}, [%4];"
                 : "=r"(r[0]), "=r"(r[1]), "=r"(r[2]), "=r"(r[3]) : "r"(addr));
}
__device__ __forceinline__ void mma16816(float* d, const uint32_t* a, const uint32_t* b) {
    asm volatile(
        "mma.sync.aligned.m16n8k16.row.col.f32.bf16.bf16.f32 "
        "{%0,%1,%2,%3}, {%4,%5,%6,%7}, {%8,%9}, {%0,%1,%2,%3};"
        : "+f"(d[0]), "+f"(d[1]), "+f"(d[2]), "+f"(d[3])
        : "r"(a[0]), "r"(a[1]), "r"(a[2]), "r"(a[3]), "r"(b[0]), "r"(b[1]));
}

// async-load a [ROWS x 128] bf16 K-major tile into smem, padded stride 272B
template <int ROWS, int NTHR>
__device__ __forceinline__ void load_tile(uint32_t sbase, const __nv_bfloat16* src,
                                          size_t row0, int nrows, int tid) {
#pragma unroll 4
    for (int c = tid; c < ROWS * 16; c += NTHR) {
        int row = c >> 4, kc = c & 15;
        uint32_t off = (uint32_t)row * 272 + kc * 16;
        size_t grow = (row < nrows) ? (row0 + row) : row0;
        cp16(sbase + off, src + grow * 128 + kc * 8, (row < nrows) ? 16 : 0);
    }
}

// ---------------- GEMM via mma.sync bf16x3 split --------------------------------
template <bool DUAL>
__global__ void __launch_bounds__(256, 1)
k_mma(const __nv_bfloat16* __restrict__ Ah, const __nv_bfloat16* __restrict__ Al,
      const __nv_bfloat16* __restrict__ Bh, const __nv_bfloat16* __restrict__ Bl,
      const float* __restrict__ a_s, const float* __restrict__ a_d,
      const float* __restrict__ a_s2, const float* __restrict__ a_d2,
      __half* __restrict__ Yh,
      float* __restrict__ asrc, float* __restrict__ adst,
      float* __restrict__ asrc2, float* __restrict__ adst2,
      int n, int ntiles) {
    constexpr int NOUT = 128;
    constexpr int NT = 16;                     // n-tiles
    constexpr int WB = NOUT * 272;             // bytes per W split half
    constexpr int AB = 128 * 272;              // bytes per A split half
    extern __shared__ __align__(16) char smem[];
    char* sWh = smem;
    char* sWl = smem + WB;
    char* sA  = smem + 2 * WB;                 // 2 bufs x (Ah | Al)
    float* sAtt = (float*)(smem + 2 * WB + 4 * AB);

    int tid = threadIdx.x, warp = tid >> 5, lane = tid & 31;

    if constexpr (DUAL) {
        for (int i = tid; i < 64; i += 256) {
            sAtt[i] = a_s[i]; sAtt[64 + i] = a_s2[i];
            sAtt[128 + i] = a_d[i]; sAtt[192 + i] = a_d2[i];
        }
    } else {
        for (int i = tid; i < NOUT; i += 256) { sAtt[i] = a_s[i]; sAtt[NOUT + i] = a_d[i]; }
    }

    uint32_t uWh = s2u(sWh), uWl = s2u(sWl), uA = s2u(sA);

    load_tile<NOUT, 256>(uWh, Bh, 0, NOUT, tid);
    load_tile<NOUT, 256>(uWl, Bl, 0, NOUT, tid);
    cp_commit();
    {
        int t0 = blockIdx.x;
        int nr = min(128, n - t0 * 128);
        load_tile<128, 256>(uA, Ah, (size_t)t0 * 128, nr, tid);
        load_tile<128, 256>(uA + AB, Al, (size_t)t0 * 128, nr, tid);
        cp_commit();
    }

    int mi = lane >> 3, l7 = lane & 7;
    uint32_t aoff = (uint32_t)(warp * 16 + ((mi & 1) << 3) + l7) * 272 + ((mi >> 1) << 3) * 2;
    uint32_t boff = (uint32_t)(((mi >> 1) << 3) + l7) * 272 + ((mi & 1) << 3) * 2;

    int buf = 0;
    for (int t = blockIdx.x; t < ntiles; t += gridDim.x) {
        int tn = t + gridDim.x;
        if (tn < ntiles) {
            int nr = min(128, n - tn * 128);
            uint32_t nb = uA + (buf ^ 1) * 2 * AB;
            load_tile<128, 256>(nb, Ah, (size_t)tn * 128, nr, tid);
            load_tile<128, 256>(nb + AB, Al, (size_t)tn * 128, nr, tid);
            cp_commit();
            cp_wait1();
        } else {
            cp_wait0();
        }
        __syncthreads();

        uint32_t uAh = uA + buf * 2 * AB;
        uint32_t uAl = uAh + AB;

        float acc[NT][4];
#pragma unroll
        for (int j = 0; j < NT; j++)
#pragma unroll
            for (int q = 0; q < 4; q++) acc[j][q] = 0.f;

#pragma unroll
        for (int ks = 0; ks < 8; ks++) {
            uint32_t kb = ks * 32;
            uint32_t ah[4], al_[4];
            ldsm4(ah, uAh + aoff + kb);
            ldsm4(al_, uAl + aoff + kb);
#pragma unroll
            for (int j = 0; j < NT; j += 2) {
                uint32_t bh[4], bl_[4];
                uint32_t bo = boff + (uint32_t)j * 8 * 272 + kb;
                ldsm4(bh, uWh + bo);
                ldsm4(bl_, uWl + bo);
                mma16816(acc[j],     ah,  bh);
                mma16816(acc[j + 1], ah,  bh + 2);
                mma16816(acc[j],     ah,  bl_);
                mma16816(acc[j + 1], ah,  bl_ + 2);
                mma16816(acc[j],     al_, bh);
                mma16816(acc[j + 1], al_, bh + 2);
            }
        }

        // epilogue
        int r0 = warp * 16 + (lane >> 2);
        int node0 = t * 128 + r0;
        int node1 = node0 + 8;
        bool v0 = node0 < n, v1 = node1 < n;
        float pa0 = 0.f, pd0 = 0.f, pa1 = 0.f, pd1 = 0.f;   // A-group (mu / full)
        float qa0 = 0.f, qd0 = 0.f, qa1 = 0.f, qd1 = 0.f;   // B-group (logstd, DUAL)
        int cb = (lane & 3) * 2;
#pragma unroll
        for (int j = 0; j < NT; j++) {
            int c = j * 8 + cb;
            float s0 = sAtt[c], s1 = sAtt[c + 1];
            float d0 = sAtt[NOUT + c], d1 = sAtt[NOUT + c + 1];
            if (DUAL && j >= NT / 2) {
                qa0 += acc[j][0] * s0 + acc[j][1] * s1;
                qd0 += acc[j][0] * d0 + acc[j][1] * d1;
                qa1 += acc[j][2] * s0 + acc[j][3] * s1;
                qd1 += acc[j][2] * d0 + acc[j][3] * d1;
            } else {
                pa0 += acc[j][0] * s0 + acc[j][1] * s1;
                pd0 += acc[j][0] * d0 + acc[j][1] * d1;
                pa1 += acc[j][2] * s0 + acc[j][3] * s1;
                pd1 += acc[j][2] * d0 + acc[j][3] * d1;
            }
            if (v0) *(__half2*)(Yh + (size_t)node0 * NOUT + c) = __floats2half2_rn(acc[j][0], acc[j][1]);
            if (v1) *(__half2*)(Yh + (size_t)node1 * NOUT + c) = __floats2half2_rn(acc[j][2], acc[j][3]);
        }
#pragma unroll
        for (int o = 1; o <= 2; o <<= 1) {
            pa0 += __shfl_xor_sync(0xffffffffu, pa0, o);
            pd0 += __shfl_xor_sync(0xffffffffu, pd0, o);
            pa1 += __shfl_xor_sync(0xffffffffu, pa1, o);
            pd1 += __shfl_xor_sync(0xffffffffu, pd1, o);
            if (DUAL) {
                qa0 += __shfl_xor_sync(0xffffffffu, qa0, o);
                qd0 += __shfl_xor_sync(0xffffffffu, qd0, o);
                qa1 += __shfl_xor_sync(0xffffffffu, qa1, o);
                qd1 += __shfl_xor_sync(0xffffffffu, qd1, o);
            }
        }
        if ((lane & 3) == 0) {
            if (v0) {
                asrc[node0] = pa0; adst[node0] = pd0;
                if (DUAL) { asrc2[node0] = qa0; adst2[node0] = qd0; }
            }
            if (v1) {
                asrc[node1] = pa1; adst[node1] = pd1;
                if (DUAL) { asrc2[node1] = qa1; adst2[node1] = qd1; }
            }
        }
        __syncthreads();
        buf ^= 1;
    }
}

// ---------------- fp32 -> bf16 hi/lo split -------------------------------------
__global__ void k_convx(const float* __restrict__ s, __nv_bfloat16* __restrict__ bh,
                        __nv_bfloat16* __restrict__ bl, int n4) {
    int i = blockIdx.x * blockDim.x + threadIdx.x;
    if (i >= n4) return;
    float4 v = ((const float4*)s)[i];
    __nv_bfloat16 h0 = __float2bfloat16(v.x), h1 = __float2bfloat16(v.y);
    __nv_bfloat16 h2 = __float2bfloat16(v.z), h3 = __float2bfloat16(v.w);
    __nv_bfloat16 l0 = __float2bfloat16(v.x - __bfloat162float(h0));
    __nv_bfloat16 l1 = __float2bfloat16(v.y - __bfloat162float(h1));
    __nv_bfloat16 l2 = __float2bfloat16(v.z - __bfloat162float(h2));
    __nv_bfloat16 l3 = __float2bfloat16(v.w - __bfloat162float(h3));
    ((__nv_bfloat162*)bh)[i * 2]     = __nv_bfloat162(h0, h1);
    ((__nv_bfloat162*)bh)[i * 2 + 1] = __nv_bfloat162(h2, h3);
    ((__nv_bfloat162*)bl)[i * 2]     = __nv_bfloat162(l0, l1);
    ((__nv_bfloat162*)bl)[i * 2 + 1] = __nv_bfloat162(l2, l3);
}

// transpose + split all 4 weight matrices into wt[n*128+k] hi/lo
__global__ void k_convw(const float* __restrict__ W0, const float* __restrict__ W1,
                        const float* __restrict__ Wm, const float* __restrict__ Wl,
                        __nv_bfloat16* __restrict__ wh, __nv_bfloat16* __restrict__ wl_) {
    int i = blockIdx.x * blockDim.x + threadIdx.x;
    if (i >= 49152) return;
    float v;
    if (i < 16384)      { int j = i;         int nn = j >> 7, k = j & 127; v = W0[k * 128 + nn]; }
    else if (i < 32768) { int j = i - 16384; int nn = j >> 7, k = j & 127; v = W1[k * 128 + nn]; }
    else if (i < 40960) { int j = i - 32768; int nn = j >> 7, k = j & 127; v = Wm[k * 64 + nn]; }
    else                { int j = i - 40960; int nn = j >> 7, k = j & 127; v = Wl[k * 64 + nn]; }
    __nv_bfloat16 h = __float2bfloat16(v);
    wh[i] = h;
    wl_[i] = __float2bfloat16(v - __bfloat162float(h));
}

// ---------------- zero scratch -------------------------------------------------
__global__ void k_zero(int* __restrict__ cnt, int* __restrict__ fill,
                       float* __restrict__ sumw, int n) {
    int i = blockIdx.x * blockDim.x + threadIdx.x;
    if (i < n) { cnt[i] = 0; fill[i] = 0; sumw[i] = 0.f; }
}

// ---------------- dtype probe --------------------------------------------------
__global__ void k_probe(const void* __restrict__ ei_raw, int* __restrict__ flag) {
    __shared__ int bad;
    if (threadIdx.x == 0) bad = 0;
    __syncthreads();
    const long long* p = (const long long*)ei_raw;
    for (int i = threadIdx.x; i < 4096; i += blockDim.x) {
        long long v = p[i];
        if (v < 0 || v >= (long long)NN) bad = 1;
    }
    __syncthreads();
    if (threadIdx.x == 0) *flag = bad ? 0 : 1;
}

// histogram of destination degrees (reads edge_index directly)
__global__ void k_hist(const void* __restrict__ ei_raw, const int* __restrict__ flag,
                       int* __restrict__ cnt, int E) {
    int e = blockIdx.x * blockDim.x + threadIdx.x;
    if (e >= E) return;
    int d;
    if (__ldg(flag)) d = (int)((const long long*)ei_raw)[E + e];
    else             d = ((const int*)ei_raw)[E + e];
    atomicAdd(&cnt[d], 1);
}

// ---------------- CSR build ---------------------------------------------------
__global__ void k_scan1(const int* __restrict__ cnt, int* __restrict__ ptr,
                        int* __restrict__ bsum, int n) {
    __shared__ int sm[SCAN_B];
    int i = blockIdx.x * SCAN_B + threadIdx.x;
    int v = (i < n) ? cnt[i] : 0;
    sm[threadIdx.x] = v;
    __syncthreads();
    for (int off = 1; off < SCAN_B; off <<= 1) {
        int t = (threadIdx.x >= off) ? sm[threadIdx.x - off] : 0;
        __syncthreads();
        sm[threadIdx.x] += t;
        __syncthreads();
    }
    if (i < n) ptr[i + 1] = sm[threadIdx.x];
    if (threadIdx.x == SCAN_B - 1) bsum[blockIdx.x] = sm[SCAN_B - 1];
    if (i == 0) ptr[0] = 0;
}

__global__ void k_scan23(int* __restrict__ ptr, const int* __restrict__ bsum, int n) {
    __shared__ int sm[128];
    int t = threadIdx.x;
    if (t < 128) sm[t] = (t < (int)blockIdx.x && t < NB_SCAN) ? bsum[t] : 0;
    __syncthreads();
    for (int off = 64; off; off >>= 1) {
        if (t < off) sm[t] += sm[t + off];
        __syncthreads();
    }
    int offs = sm[0];
    int i = blockIdx.x * SCAN_B + t;
    if (i < n) ptr[i + 1] += offs;
}

__global__ void k_scatter(const void* __restrict__ ei_raw, const int* __restrict__ flag,
                          const float* __restrict__ ew,
                          const int* __restrict__ ptr, int* __restrict__ fill,
                          int* __restrict__ csrc, float* __restrict__ csw,
                          float* __restrict__ sumw, int E) {
    int e = blockIdx.x * blockDim.x + threadIdx.x;
    if (e >= E) return;
    int s, d;
    if (__ldg(flag)) {
        const long long* p = (const long long*)ei_raw;
        s = (int)p[e]; d = (int)p[E + e];
    } else {
        const int* p = (const int*)ei_raw;
        s = p[e]; d = p[E + e];
    }
    float w = ew[e];
    int pos = ptr[d] + atomicAdd(&fill[d], 1);
    csrc[pos] = s;
    csw[pos] = w;
    atomicAdd(&sumw[d], w);
}

// fused: 3 edge-attention dots (block 0) + self-loop attr (blocks 1..)
__global__ void k_misc(const int* __restrict__ cnt, const float* __restrict__ sumw,
                       float* __restrict__ la,
                       const float* __restrict__ We0, const float* __restrict__ ae0,
                       const float* __restrict__ We1, const float* __restrict__ ae1,
                       const float* __restrict__ Wem, const float* __restrict__ aem,
                       float* __restrict__ c, int n) {
    if (blockIdx.x == 0) {
        int w = threadIdx.x >> 5, lane = threadIdx.x & 31;
        if (w < 3) {
            const float* A = (w == 0) ? We0 : ((w == 1) ? We1 : Wem);
            const float* B = (w == 0) ? ae0 : ((w == 1) ? ae1 : aem);
            int len = (w == 2) ? 64 : 128;
            float p = 0.f;
            for (int i = lane; i < len; i += 32) p += A[i] * B[i];
#pragma unroll
            for (int off = 16; off; off >>= 1) p += __shfl_xor_sync(0xffffffffu, p, off);
            if (lane == 0) c[w] = p;
        }
    } else {
        int i = (blockIdx.x - 1) * blockDim.x + threadIdx.x;
        if (i < n) {
            int cc = cnt[i];
            la[i] = (cc > 0) ? (sumw[i] / (float)cc) : 0.0f;
        }
    }
}

// ---------------- aggregation (layers 0/1): quarter-warp per node --------------
// 8-lane sub-warps: lane covers 16 fp16 cols via 2 independent float4 loads;
// 4 nodes in flight per warp. Segment-masked shuffles (trip counts diverge).
__device__ __forceinline__ float lrelu(float a) { return a > 0.f ? a : 0.2f * a; }

__global__ void k_aggregate(const __half* __restrict__ xl, const float* __restrict__ asrc,
                            const float* __restrict__ adst, const int* __restrict__ ptr,
                            const int* __restrict__ csrc, const float* __restrict__ csw,
                            const float* __restrict__ la, const float* __restrict__ cvec,
                            int cidx, const float* __restrict__ bias,
                            __nv_bfloat16* __restrict__ obh, __nv_bfloat16* __restrict__ obl,
                            int n) {
    int qw = (blockIdx.x * blockDim.x + threadIdx.x) >> 3;
    int l = threadIdx.x & 7;
    uint32_t smask = 0xFFu << (threadIdx.x & 24);   // this 8-lane segment only
    if (qw >= n) return;
    int v = qw;

    float c = cvec[cidx];
    float adv = adst[v];
    float a0 = lrelu(asrc[v] + adv + la[v] * c);
    int rs = ptr[v], re = ptr[v + 1];

    // pass A: exact max over self-loop + incoming edges
    float m = a0;
    for (int e = rs + l; e < re; e += 8)
        m = fmaxf(m, lrelu(asrc[csrc[e]] + adv + csw[e] * c));
#pragma unroll
    for (int o = 4; o; o >>= 1) m = fmaxf(m, __shfl_xor_sync(smask, m, o, 8));

    // pass B: fixed weights; lane covers cols [l*16, l*16+16) via 2 float4 loads
    float w0 = __expf(a0 - m);
    float denp = (l == 0) ? w0 : 0.f;
    float acc[16];
    {
        const float4* rp = (const float4*)(xl + (size_t)v * 128);
        float4 r0 = rp[l * 2], r1 = rp[l * 2 + 1];
        const __half2* h0 = (const __half2*)&r0;
        const __half2* h1 = (const __half2*)&r1;
#pragma unroll
        for (int i = 0; i < 4; i++) {
            float2 f0 = __half22float2(h0[i]);
            float2 f1 = __half22float2(h1[i]);
            acc[i * 2] = w0 * f0.x; acc[i * 2 + 1] = w0 * f0.y;
            acc[8 + i * 2] = w0 * f1.x; acc[8 + i * 2 + 1] = w0 * f1.y;
        }
    }
    for (int b = rs; b < re; b += 8) {
        int e = b + l;
        float w = 0.f;
        int sIdx = 0;
        if (e < re) {
            sIdx = csrc[e];
            w = __expf(lrelu(asrc[sIdx] + adv + csw[e] * c) - m);
        }
        denp += w;
        int cnt = min(8, re - b);
#pragma unroll 4
        for (int j = 0; j < cnt; j++) {
            float wj = __shfl_sync(smask, w, j, 8);
            int sj = __shfl_sync(smask, sIdx, j, 8);
            const float4* rp = (const float4*)(xl + (size_t)sj * 128);
            float4 r0 = rp[l * 2], r1 = rp[l * 2 + 1];
            const __half2* h0 = (const __half2*)&r0;
            const __half2* h1 = (const __half2*)&r1;
#pragma unroll
            for (int i = 0; i < 4; i++) {
                float2 f0 = __half22float2(h0[i]);
                float2 f1 = __half22float2(h1[i]);
                acc[i * 2] += wj * f0.x; acc[i * 2 + 1] += wj * f0.y;
                acc[8 + i * 2] += wj * f1.x; acc[8 + i * 2 + 1] += wj * f1.y;
            }
        }
    }
#pragma unroll
    for (int o = 4; o; o >>= 1) denp += __shfl_xor_sync(smask, denp, o, 8);
    float inv = 1.0f / denp;

    const float4* bp = (const float4*)bias;
    __nv_bfloat162* ph = (__nv_bfloat162*)(obh + (size_t)v * 128) + l * 8;
    __nv_bfloat162* pl = (__nv_bfloat162*)(obl + (size_t)v * 128) + l * 8;
#pragma unroll
    for (int q = 0; q < 4; q++) {
        float4 bv = bp[l * 4 + q];
        float o0 = fmaxf(acc[q * 4 + 0] * inv + bv.x, 0.f);
        float o1 = fmaxf(acc[q * 4 + 1] * inv + bv.y, 0.f);
        float o2 = fmaxf(acc[q * 4 + 2] * inv + bv.z, 0.f);
        float o3 = fmaxf(acc[q * 4 + 3] * inv + bv.w, 0.f);
        __nv_bfloat16 h0 = __float2bfloat16(o0), h1 = __float2bfloat16(o1);
        __nv_bfloat16 h2 = __float2bfloat16(o2), h3 = __float2bfloat16(o3);
        ph[q * 2]     = __nv_bfloat162(h0, h1);
        ph[q * 2 + 1] = __nv_bfloat162(h2, h3);
        pl[q * 2]     = __nv_bfloat162(__float2bfloat16(o0 - __bfloat162float(h0)),
                                       __float2bfloat16(o1 - __bfloat162float(h1)));
        pl[q * 2 + 1] = __nv_bfloat162(__float2bfloat16(o2 - __bfloat162float(h2)),
                                       __float2bfloat16(o3 - __bfloat162float(h3)));
    }
}

// ---------------- fused mu+logstd aggregation: quarter-warp per node -----------
// Lane l covers cols [16l, 16l+16); lanes 0-3 = mu (cols 0-63), 4-7 = logstd.
__global__ void k_aggdual(const __half* __restrict__ xl,
                          const float* __restrict__ asrcA, const float* __restrict__ adstA,
                          const float* __restrict__ asrcB, const float* __restrict__ adstB,
                          const int* __restrict__ ptr, const int* __restrict__ csrc,
                          const float* __restrict__ csw, const float* __restrict__ la,
                          const float* __restrict__ cvec,
                          const float* __restrict__ biasA, const float* __restrict__ biasB,
                          float* __restrict__ outA, float* __restrict__ outB, int n) {
    int qw = (blockIdx.x * blockDim.x + threadIdx.x) >> 3;
    int l = threadIdx.x & 7;
    uint32_t smask = 0xFFu << (threadIdx.x & 24);
    if (qw >= n) return;
    int v = qw;
    bool isA = l < 4;

    float c = cvec[2];
    float advA = adstA[v], advB = adstB[v];
    float lav = la[v];

    float a0A = lrelu(asrcA[v] + advA + lav * c);
    float a0B = lrelu(asrcB[v] + advB);
    int rs = ptr[v], re = ptr[v + 1];

    float mA = a0A, mB = a0B;
    for (int e = rs + l; e < re; e += 8) {
        int s = csrc[e];
        mA = fmaxf(mA, lrelu(asrcA[s] + advA + csw[e] * c));
        mB = fmaxf(mB, lrelu(asrcB[s] + advB));
    }
#pragma unroll
    for (int o = 4; o; o >>= 1) {
        mA = fmaxf(mA, __shfl_xor_sync(smask, mA, o, 8));
        mB = fmaxf(mB, __shfl_xor_sync(smask, mB, o, 8));
    }

    float w0A = __expf(a0A - mA), w0B = __expf(a0B - mB);
    float denA = (l == 0) ? w0A : 0.f;
    float denB = (l == 0) ? w0B : 0.f;
    float wsel0 = isA ? w0A : w0B;
    float acc[16];
    {
        const float4* rp = (const float4*)(xl + (size_t)v * 128);
        float4 r0 = rp[l * 2], r1 = rp[l * 2 + 1];
        const __half2* h0 = (const __half2*)&r0;
        const __half2* h1 = (const __half2*)&r1;
#pragma unroll
        for (int i = 0; i < 4; i++) {
            float2 f0 = __half22float2(h0[i]);
            float2 f1 = __half22float2(h1[i]);
            acc[i * 2] = wsel0 * f0.x; acc[i * 2 + 1] = wsel0 * f0.y;
            acc[8 + i * 2] = wsel0 * f1.x; acc[8 + i * 2 + 1] = wsel0 * f1.y;
        }
    }
    for (int b = rs; b < re; b += 8) {
        int e = b + l;
        float wA = 0.f, wB = 0.f;
        int sIdx = 0;
        if (e < re) {
            sIdx = csrc[e];
            wA = __expf(lrelu(asrcA[sIdx] + advA + csw[e] * c) - mA);
            wB = __expf(lrelu(asrcB[sIdx] + advB) - mB);
        }
        denA += wA; denB += wB;
        int cnt = min(8, re - b);
#pragma unroll 4
        for (int j = 0; j < cnt; j++) {
            float wjA = __shfl_sync(smask, wA, j, 8);
            float wjB = __shfl_sync(smask, wB, j, 8);
            int sj = __shfl_sync(smask, sIdx, j, 8);
            float wj = isA ? wjA : wjB;
            const float4* rp = (const float4*)(xl + (size_t)sj * 128);
            float4 r0 = rp[l * 2], r1 = rp[l * 2 + 1];
            const __half2* h0 = (const __half2*)&r0;
            const __half2* h1 = (const __half2*)&r1;
#pragma unroll
            for (int i = 0; i < 4; i++) {
                float2 f0 = __half22float2(h0[i]);
                float2 f1 = __half22float2(h1[i]);
                acc[i * 2] += wj * f0.x; acc[i * 2 + 1] += wj * f0.y;
                acc[8 + i * 2] += wj * f1.x; acc[8 + i * 2 + 1] += wj * f1.y;
            }
        }
    }
#pragma unroll
    for (int o = 4; o; o >>= 1) {
        denA += __shfl_xor_sync(smask, denA, o, 8);
        denB += __shfl_xor_sync(smask, denB, o, 8);
    }
    float inv = isA ? (1.0f / denA) : (1.0f / denB);

    const float4* bp = isA ? (const float4*)biasA : (const float4*)biasB;
    int lb = isA ? l : (l - 4);
    float* dst = (isA ? outA : outB) + (size_t)v * 64 + lb * 16;
#pragma unroll
    for (int q = 0; q < 4; q++) {
        float4 bv = bp[lb * 4 + q];
        ((float4*)dst)[q] = make_float4(acc[q * 4 + 0] * inv + bv.x,
                                        acc[q * 4 + 1] * inv + bv.y,
                                        acc[q * 4 + 2] * inv + bv.z,
                                        acc[q * 4 + 3] * inv + bv.w);
    }
}

// ---------------- launch ------------------------------------------------------
extern "C" void kernel_launch(void* const* d_in, const int* in_sizes, int n_in,
                              void* d_out, int out_size) {
    const float* x      = (const float*)d_in[0];
    const void*  ei_raw = d_in[1];          // int32 or int64, probed at runtime
    const float* ew     = (const float*)d_in[2];
    const float *W0 = (const float*)d_in[3],  *as0 = (const float*)d_in[4],
                *ad0 = (const float*)d_in[5], *ae0 = (const float*)d_in[6],
                *We0 = (const float*)d_in[7], *b0  = (const float*)d_in[8];
    const float *W1 = (const float*)d_in[9],  *as1 = (const float*)d_in[10],
                *ad1 = (const float*)d_in[11], *ae1 = (const float*)d_in[12],
                *We1 = (const float*)d_in[13], *b1  = (const float*)d_in[14];
    const float *Wm = (const float*)d_in[15], *asm_ = (const float*)d_in[16],
                *adm = (const float*)d_in[17], *aem = (const float*)d_in[18],
                *Wem = (const float*)d_in[19], *bm  = (const float*)d_in[20];
    const float *Wl = (const float*)d_in[21], *asl = (const float*)d_in[22],
                *adl = (const float*)d_in[23], *bl  = (const float*)d_in[24];
    float* out = (float*)d_out;

    int *p_flag, *p_cnt, *p_fill, *p_ptr, *p_bsum, *p_csrc;
    float *p_csw, *p_sumw, *p_loop, *p_xl, *p_asrc, *p_adst, *p_asrc2, *p_adst2, *p_c;
    __nv_bfloat16 *p_bh, *p_bl, *p_wh, *p_wl;
    cudaGetSymbolAddress((void**)&p_flag, g_flag64);
    cudaGetSymbolAddress((void**)&p_cnt,  g_cnt);
    cudaGetSymbolAddress((void**)&p_fill, g_fill);
    cudaGetSymbolAddress((void**)&p_ptr,  g_ptr);
    cudaGetSymbolAddress((void**)&p_bsum, g_bsum);
    cudaGetSymbolAddress((void**)&p_csrc, g_csrc);
    cudaGetSymbolAddress((void**)&p_csw,  g_csw);
    cudaGetSymbolAddress((void**)&p_sumw, g_sumw);
    cudaGetSymbolAddress((void**)&p_loop, g_loop);
    cudaGetSymbolAddress((void**)&p_xl,   g_xl);
    cudaGetSymbolAddress((void**)&p_asrc, g_asrc);
    cudaGetSymbolAddress((void**)&p_adst, g_adst);
    cudaGetSymbolAddress((void**)&p_asrc2, g_asrc2);
    cudaGetSymbolAddress((void**)&p_adst2, g_adst2);
    cudaGetSymbolAddress((void**)&p_c,    g_c);
    cudaGetSymbolAddress((void**)&p_bh,   g_bh);
    cudaGetSymbolAddress((void**)&p_bl,   g_bl);
    cudaGetSymbolAddress((void**)&p_wh,   g_wh);
    cudaGetSymbolAddress((void**)&p_wl,   g_wl);
    __half* p_xlh = (__half*)p_xl;       // fp16 alias (all layers)

    const int sm128 = 2 * (128 * 272) + 4 * (128 * 272) + 2 * 128 * 4;
    cudaFuncSetAttribute(k_mma<false>, cudaFuncAttributeMaxDynamicSharedMemorySize, sm128);
    cudaFuncSetAttribute(k_mma<true>,  cudaFuncAttributeMaxDynamicSharedMemorySize, sm128);

    const int agg_blocks = (NN + 31) / 32;   // 32 quarter-warps/block, 8 lanes per node
    const int cx_blocks  = (NN * 128 / 4 + 255) / 256;

    // 1: weight transpose + bf16 split
    k_convw<<<(49152 + 255) / 256, 256>>>(W0, W1, Wm, Wl, p_wh, p_wl);
    // 2: split input x
    k_convx<<<cx_blocks, 256>>>(x, p_bh, p_bl, NN * 128 / 4);
    // 3: zero scratch
    k_zero<<<(NN + 255) / 256, 256>>>(p_cnt, p_fill, p_sumw, NN);
    // 4: layer-0 GEMM (profiled slot) -> fp16 xl
    k_mma<false><<<MMA_GRID, 256, sm128>>>(p_bh, p_bl, p_wh, p_wl, as0, ad0,
                                           nullptr, nullptr, p_xlh,
                                           p_asrc, p_adst, nullptr, nullptr, NN, NTILES);
    // 5-9: CSR build
    k_probe<<<1, 256>>>(ei_raw, p_flag);
    k_hist<<<(NE + 511) / 512, 512>>>(ei_raw, p_flag, p_cnt, NE);
    k_scan1<<<NB_SCAN, SCAN_B>>>(p_cnt, p_ptr, p_bsum, NN);
    k_scan23<<<NB_SCAN, SCAN_B>>>(p_ptr, p_bsum, NN);
    k_scatter<<<(NE + 511) / 512, 512>>>(ei_raw, p_flag, ew, p_ptr, p_fill,
                                         p_csrc, p_csw, p_sumw, NE);
    // 10: edge-attention scalars + self-loop attrs
    k_misc<<<1 + (NN + 255) / 256, 256>>>(p_cnt, p_sumw, p_loop,
                                          We0, ae0, We1, ae1, Wem, aem, p_c, NN);

    // layer 0 aggregate (fp16 gather) -> bf16 split
    k_aggregate<<<agg_blocks, 256>>>(p_xlh, p_asrc, p_adst, p_ptr, p_csrc, p_csw,
                                     p_loop, p_c, 0, b0, p_bh, p_bl, NN);
    // layer 1
    k_mma<false><<<MMA_GRID, 256, sm128>>>(p_bh, p_bl, p_wh + 16384, p_wl + 16384, as1, ad1,
                                           nullptr, nullptr, p_xlh,
                                           p_asrc, p_adst, nullptr, nullptr, NN, NTILES);
    k_aggregate<<<agg_blocks, 256>>>(p_xlh, p_asrc, p_adst, p_ptr, p_csrc, p_csw,
                                     p_loop, p_c, 1, b1, p_bh, p_bl, NN);
    // mu+logstd fused GEMM (combined weights at offset 32768) -> fp16 xl
    k_mma<true><<<MMA_GRID, 256, sm128>>>(p_bh, p_bl, p_wh + 32768, p_wl + 32768,
                                          asm_, adm, asl, adl, p_xlh,
                                          p_asrc, p_adst, p_asrc2, p_adst2, NN, NTILES);
    // fused mu+logstd aggregation (fp16 gather)
    k_aggdual<<<agg_blocks, 256>>>(p_xlh, p_asrc, p_adst, p_asrc2, p_adst2,
                                   p_ptr, p_csrc, p_csw, p_loop, p_c,
                                   bm, bl, out, out + (size_t)NN * 64, NN);
}

// round 16
// speedup vs baseline: 1.0987x; 1.0987x over previous
#include <cuda_runtime.h>
#include <cuda_bf16.h>
#include <cuda_fp16.h>
#include <cstdint>

// Problem constants (fixed by the dataset)
#define NN 100000
#define NE 1600000
#define SCAN_B 1024
#define NB_SCAN ((NN + SCAN_B - 1) / SCAN_B)   // 98
#define NTILES ((NN + 127) / 128)              // 782
#define MMA_GRID 148

// ---------------- scratch (device globals; no allocation allowed) -------------
__device__ int   g_flag64;           // 1 if edge_index buffer is int64
__device__ int   g_cnt[NN];
__device__ int   g_fill[NN];
__device__ int   g_ptr[NN + 1];
__device__ int   g_bsum[128];
__device__ int   g_csrc[NE];
__device__ float g_csw[NE];
__device__ float g_sumw[NN];
__device__ float g_loop[NN];
__device__ float g_xl[(size_t)NN * 128];   // aliased as half (all layers gather fp16)
__device__ float g_asrc[NN];
__device__ float g_adst[NN];
__device__ float g_asrc2[NN];
__device__ float g_adst2[NN];
__device__ float g_c[4];
__device__ __nv_bfloat16 g_bh[(size_t)NN * 128];
__device__ __nv_bfloat16 g_bl[(size_t)NN * 128];
__device__ __nv_bfloat16 g_wh[49152];
__device__ __nv_bfloat16 g_wl[49152];

// ---------------- helpers -------------------------------------------------------
__device__ __forceinline__ uint32_t s2u(const void* p) {
    uint32_t a;
    asm("{ .reg .u64 t; cvta.to.shared.u64 t, %1; cvt.u32.u64 %0, t; }"
        : "=r"(a) : "l"(p));
    return a;
}
__device__ __forceinline__ void cp16(uint32_t saddr, const void* g, int sz) {
    asm volatile("cp.async.cg.shared.global [%0], [%1], 16, %2;"
                 :: "r"(saddr), "l"(g), "r"(sz));
}
__device__ __forceinline__ void cp_commit() {
    asm volatile("cp.async.commit_group;" ::: "memory");
}
__device__ __forceinline__ void cp_wait1() {
    asm volatile("cp.async.wait_group 1;" ::: "memory");
}
__device__ __forceinline__ void cp_wait0() {
    asm volatile("cp.async.wait_group 0;" ::: "memory");
}
__device__ __forceinline__ void ldsm4(uint32_t* r, uint32_t addr) {
    asm volatile("ldmatrix.sync.aligned.m8n8.x4.shared.b16 {%0,%1,%2,%3}, [%4];"
                 : "=r"(r[0]), "=r"(r[1]), "=r"(r[2]), "=r"(r[3]) : "r"(addr));
}
__device__ __forceinline__ void mma16816(float* d, const uint32_t* a, const uint32_t* b) {
    asm volatile(
        "mma.sync.aligned.m16n8k16.row.col.f32.bf16.bf16.f32 "
        "{%0,%1,%2,%3}, {%4,%5,%6,%7}, {%8,%9}, {%0,%1,%2,%3};"
        : "+f"(d[0]), "+f"(d[1]), "+f"(d[2]), "+f"(d[3])
        : "r"(a[0]), "r"(a[1]), "r"(a[2]), "r"(a[3]), "r"(b[0]), "r"(b[1]));
}

// async-load a [ROWS x 128] bf16 K-major tile into smem, padded stride 272B
template <int ROWS, int NTHR>
__device__ __forceinline__ void load_tile(uint32_t sbase, const __nv_bfloat16* src,
                                          size_t row0, int nrows, int tid) {
#pragma unroll 4
    for (int c = tid; c < ROWS * 16; c += NTHR) {
        int row = c >> 4, kc = c & 15;
        uint32_t off = (uint32_t)row * 272 + kc * 16;
        size_t grow = (row < nrows) ? (row0 + row) : row0;
        cp16(sbase + off, src + grow * 128 + kc * 8, (row < nrows) ? 16 : 0);
    }
}

// ---------------- GEMM via mma.sync bf16x3 split --------------------------------
template <bool DUAL>
__global__ void __launch_bounds__(256, 1)
k_mma(const __nv_bfloat16* __restrict__ Ah, const __nv_bfloat16* __restrict__ Al,
      const __nv_bfloat16* __restrict__ Bh, const __nv_bfloat16* __restrict__ Bl,
      const float* __restrict__ a_s, const float* __restrict__ a_d,
      const float* __restrict__ a_s2, const float* __restrict__ a_d2,
      __half* __restrict__ Yh,
      float* __restrict__ asrc, float* __restrict__ adst,
      float* __restrict__ asrc2, float* __restrict__ adst2,
      int n, int ntiles) {
    constexpr int NOUT = 128;
    constexpr int NT = 16;                     // n-tiles
    constexpr int WB = NOUT * 272;             // bytes per W split half
    constexpr int AB = 128 * 272;              // bytes per A split half
    extern __shared__ __align__(16) char smem[];
    char* sWh = smem;
    char* sWl = smem + WB;
    char* sA  = smem + 2 * WB;                 // 2 bufs x (Ah | Al)
    float* sAtt = (float*)(smem + 2 * WB + 4 * AB);

    int tid = threadIdx.x, warp = tid >> 5, lane = tid & 31;

    if constexpr (DUAL) {
        for (int i = tid; i < 64; i += 256) {
            sAtt[i] = a_s[i]; sAtt[64 + i] = a_s2[i];
            sAtt[128 + i] = a_d[i]; sAtt[192 + i] = a_d2[i];
        }
    } else {
        for (int i = tid; i < NOUT; i += 256) { sAtt[i] = a_s[i]; sAtt[NOUT + i] = a_d[i]; }
    }

    uint32_t uWh = s2u(sWh), uWl = s2u(sWl), uA = s2u(sA);

    load_tile<NOUT, 256>(uWh, Bh, 0, NOUT, tid);
    load_tile<NOUT, 256>(uWl, Bl, 0, NOUT, tid);
    cp_commit();
    {
        int t0 = blockIdx.x;
        int nr = min(128, n - t0 * 128);
        load_tile<128, 256>(uA, Ah, (size_t)t0 * 128, nr, tid);
        load_tile<128, 256>(uA + AB, Al, (size_t)t0 * 128, nr, tid);
        cp_commit();
    }

    int mi = lane >> 3, l7 = lane & 7;
    uint32_t aoff = (uint32_t)(warp * 16 + ((mi & 1) << 3) + l7) * 272 + ((mi >> 1) << 3) * 2;
    uint32_t boff = (uint32_t)(((mi >> 1) << 3) + l7) * 272 + ((mi & 1) << 3) * 2;

    int buf = 0;
    for (int t = blockIdx.x; t < ntiles; t += gridDim.x) {
        int tn = t + gridDim.x;
        if (tn < ntiles) {
            int nr = min(128, n - tn * 128);
            uint32_t nb = uA + (buf ^ 1) * 2 * AB;
            load_tile<128, 256>(nb, Ah, (size_t)tn * 128, nr, tid);
            load_tile<128, 256>(nb + AB, Al, (size_t)tn * 128, nr, tid);
            cp_commit();
            cp_wait1();
        } else {
            cp_wait0();
        }
        __syncthreads();

        uint32_t uAh = uA + buf * 2 * AB;
        uint32_t uAl = uAh + AB;

        float acc[NT][4];
#pragma unroll
        for (int j = 0; j < NT; j++)
#pragma unroll
            for (int q = 0; q < 4; q++) acc[j][q] = 0.f;

#pragma unroll
        for (int ks = 0; ks < 8; ks++) {
            uint32_t kb = ks * 32;
            uint32_t ah[4], al_[4];
            ldsm4(ah, uAh + aoff + kb);
            ldsm4(al_, uAl + aoff + kb);
#pragma unroll
            for (int j = 0; j < NT; j += 2) {
                uint32_t bh[4], bl_[4];
                uint32_t bo = boff + (uint32_t)j * 8 * 272 + kb;
                ldsm4(bh, uWh + bo);
                ldsm4(bl_, uWl + bo);
                mma16816(acc[j],     ah,  bh);
                mma16816(acc[j + 1], ah,  bh + 2);
                mma16816(acc[j],     ah,  bl_);
                mma16816(acc[j + 1], ah,  bl_ + 2);
                mma16816(acc[j],     al_, bh);
                mma16816(acc[j + 1], al_, bh + 2);
            }
        }

        // epilogue
        int r0 = warp * 16 + (lane >> 2);
        int node0 = t * 128 + r0;
        int node1 = node0 + 8;
        bool v0 = node0 < n, v1 = node1 < n;
        float pa0 = 0.f, pd0 = 0.f, pa1 = 0.f, pd1 = 0.f;   // A-group (mu / full)
        float qa0 = 0.f, qd0 = 0.f, qa1 = 0.f, qd1 = 0.f;   // B-group (logstd, DUAL)
        int cb = (lane & 3) * 2;
#pragma unroll
        for (int j = 0; j < NT; j++) {
            int c = j * 8 + cb;
            float s0 = sAtt[c], s1 = sAtt[c + 1];
            float d0 = sAtt[NOUT + c], d1 = sAtt[NOUT + c + 1];
            if (DUAL && j >= NT / 2) {
                qa0 += acc[j][0] * s0 + acc[j][1] * s1;
                qd0 += acc[j][0] * d0 + acc[j][1] * d1;
                qa1 += acc[j][2] * s0 + acc[j][3] * s1;
                qd1 += acc[j][2] * d0 + acc[j][3] * d1;
            } else {
                pa0 += acc[j][0] * s0 + acc[j][1] * s1;
                pd0 += acc[j][0] * d0 + acc[j][1] * d1;
                pa1 += acc[j][2] * s0 + acc[j][3] * s1;
                pd1 += acc[j][2] * d0 + acc[j][3] * d1;
            }
            if (v0) *(__half2*)(Yh + (size_t)node0 * NOUT + c) = __floats2half2_rn(acc[j][0], acc[j][1]);
            if (v1) *(__half2*)(Yh + (size_t)node1 * NOUT + c) = __floats2half2_rn(acc[j][2], acc[j][3]);
        }
#pragma unroll
        for (int o = 1; o <= 2; o <<= 1) {
            pa0 += __shfl_xor_sync(0xffffffffu, pa0, o);
            pd0 += __shfl_xor_sync(0xffffffffu, pd0, o);
            pa1 += __shfl_xor_sync(0xffffffffu, pa1, o);
            pd1 += __shfl_xor_sync(0xffffffffu, pd1, o);
            if (DUAL) {
                qa0 += __shfl_xor_sync(0xffffffffu, qa0, o);
                qd0 += __shfl_xor_sync(0xffffffffu, qd0, o);
                qa1 += __shfl_xor_sync(0xffffffffu, qa1, o);
                qd1 += __shfl_xor_sync(0xffffffffu, qd1, o);
            }
        }
        if ((lane & 3) == 0) {
            if (v0) {
                asrc[node0] = pa0; adst[node0] = pd0;
                if (DUAL) { asrc2[node0] = qa0; adst2[node0] = qd0; }
            }
            if (v1) {
                asrc[node1] = pa1; adst[node1] = pd1;
                if (DUAL) { asrc2[node1] = qa1; adst2[node1] = qd1; }
            }
        }
        __syncthreads();
        buf ^= 1;
    }
}

// ---------------- fp32 -> bf16 hi/lo split -------------------------------------
__global__ void k_convx(const float* __restrict__ s, __nv_bfloat16* __restrict__ bh,
                        __nv_bfloat16* __restrict__ bl, int n4) {
    int i = blockIdx.x * blockDim.x + threadIdx.x;
    if (i >= n4) return;
    float4 v = ((const float4*)s)[i];
    __nv_bfloat16 h0 = __float2bfloat16(v.x), h1 = __float2bfloat16(v.y);
    __nv_bfloat16 h2 = __float2bfloat16(v.z), h3 = __float2bfloat16(v.w);
    __nv_bfloat16 l0 = __float2bfloat16(v.x - __bfloat162float(h0));
    __nv_bfloat16 l1 = __float2bfloat16(v.y - __bfloat162float(h1));
    __nv_bfloat16 l2 = __float2bfloat16(v.z - __bfloat162float(h2));
    __nv_bfloat16 l3 = __float2bfloat16(v.w - __bfloat162float(h3));
    ((__nv_bfloat162*)bh)[i * 2]     = __nv_bfloat162(h0, h1);
    ((__nv_bfloat162*)bh)[i * 2 + 1] = __nv_bfloat162(h2, h3);
    ((__nv_bfloat162*)bl)[i * 2]     = __nv_bfloat162(l0, l1);
    ((__nv_bfloat162*)bl)[i * 2 + 1] = __nv_bfloat162(l2, l3);
}

// transpose + split all 4 weight matrices into wt[n*128+k] hi/lo
__global__ void k_convw(const float* __restrict__ W0, const float* __restrict__ W1,
                        const float* __restrict__ Wm, const float* __restrict__ Wl,
                        __nv_bfloat16* __restrict__ wh, __nv_bfloat16* __restrict__ wl_) {
    int i = blockIdx.x * blockDim.x + threadIdx.x;
    if (i >= 49152) return;
    float v;
    if (i < 16384)      { int j = i;         int nn = j >> 7, k = j & 127; v = W0[k * 128 + nn]; }
    else if (i < 32768) { int j = i - 16384; int nn = j >> 7, k = j & 127; v = W1[k * 128 + nn]; }
    else if (i < 40960) { int j = i - 32768; int nn = j >> 7, k = j & 127; v = Wm[k * 64 + nn]; }
    else                { int j = i - 40960; int nn = j >> 7, k = j & 127; v = Wl[k * 64 + nn]; }
    __nv_bfloat16 h = __float2bfloat16(v);
    wh[i] = h;
    wl_[i] = __float2bfloat16(v - __bfloat162float(h));
}

// ---------------- zero scratch -------------------------------------------------
__global__ void k_zero(int* __restrict__ cnt, int* __restrict__ fill,
                       float* __restrict__ sumw, int n) {
    int i = blockIdx.x * blockDim.x + threadIdx.x;
    if (i < n) { cnt[i] = 0; fill[i] = 0; sumw[i] = 0.f; }
}

// ---------------- dtype probe --------------------------------------------------
__global__ void k_probe(const void* __restrict__ ei_raw, int* __restrict__ flag) {
    __shared__ int bad;
    if (threadIdx.x == 0) bad = 0;
    __syncthreads();
    const long long* p = (const long long*)ei_raw;
    for (int i = threadIdx.x; i < 4096; i += blockDim.x) {
        long long v = p[i];
        if (v < 0 || v >= (long long)NN) bad = 1;
    }
    __syncthreads();
    if (threadIdx.x == 0) *flag = bad ? 0 : 1;
}

// histogram of destination degrees (reads edge_index directly)
__global__ void k_hist(const void* __restrict__ ei_raw, const int* __restrict__ flag,
                       int* __restrict__ cnt, int E) {
    int e = blockIdx.x * blockDim.x + threadIdx.x;
    if (e >= E) return;
    int d;
    if (__ldg(flag)) d = (int)((const long long*)ei_raw)[E + e];
    else             d = ((const int*)ei_raw)[E + e];
    atomicAdd(&cnt[d], 1);
}

// ---------------- CSR build ---------------------------------------------------
__global__ void k_scan1(const int* __restrict__ cnt, int* __restrict__ ptr,
                        int* __restrict__ bsum, int n) {
    __shared__ int sm[SCAN_B];
    int i = blockIdx.x * SCAN_B + threadIdx.x;
    int v = (i < n) ? cnt[i] : 0;
    sm[threadIdx.x] = v;
    __syncthreads();
    for (int off = 1; off < SCAN_B; off <<= 1) {
        int t = (threadIdx.x >= off) ? sm[threadIdx.x - off] : 0;
        __syncthreads();
        sm[threadIdx.x] += t;
        __syncthreads();
    }
    if (i < n) ptr[i + 1] = sm[threadIdx.x];
    if (threadIdx.x == SCAN_B - 1) bsum[blockIdx.x] = sm[SCAN_B - 1];
    if (i == 0) ptr[0] = 0;
}

__global__ void k_scan23(int* __restrict__ ptr, const int* __restrict__ bsum, int n) {
    __shared__ int sm[128];
    int t = threadIdx.x;
    if (t < 128) sm[t] = (t < (int)blockIdx.x && t < NB_SCAN) ? bsum[t] : 0;
    __syncthreads();
    for (int off = 64; off; off >>= 1) {
        if (t < off) sm[t] += sm[t + off];
        __syncthreads();
    }
    int offs = sm[0];
    int i = blockIdx.x * SCAN_B + t;
    if (i < n) ptr[i + 1] += offs;
}

__global__ void k_scatter(const void* __restrict__ ei_raw, const int* __restrict__ flag,
                          const float* __restrict__ ew,
                          const int* __restrict__ ptr, int* __restrict__ fill,
                          int* __restrict__ csrc, float* __restrict__ csw,
                          float* __restrict__ sumw, int E) {
    int e = blockIdx.x * blockDim.x + threadIdx.x;
    if (e >= E) return;
    int s, d;
    if (__ldg(flag)) {
        const long long* p = (const long long*)ei_raw;
        s = (int)p[e]; d = (int)p[E + e];
    } else {
        const int* p = (const int*)ei_raw;
        s = p[e]; d = p[E + e];
    }
    float w = ew[e];
    int pos = ptr[d] + atomicAdd(&fill[d], 1);
    csrc[pos] = s;
    csw[pos] = w;
    atomicAdd(&sumw[d], w);
}

// fused: 3 edge-attention dots (block 0) + self-loop attr (blocks 1..)
__global__ void k_misc(const int* __restrict__ cnt, const float* __restrict__ sumw,
                       float* __restrict__ la,
                       const float* __restrict__ We0, const float* __restrict__ ae0,
                       const float* __restrict__ We1, const float* __restrict__ ae1,
                       const float* __restrict__ Wem, const float* __restrict__ aem,
                       float* __restrict__ c, int n) {
    if (blockIdx.x == 0) {
        int w = threadIdx.x >> 5, lane = threadIdx.x & 31;
        if (w < 3) {
            const float* A = (w == 0) ? We0 : ((w == 1) ? We1 : Wem);
            const float* B = (w == 0) ? ae0 : ((w == 1) ? ae1 : aem);
            int len = (w == 2) ? 64 : 128;
            float p = 0.f;
            for (int i = lane; i < len; i += 32) p += A[i] * B[i];
#pragma unroll
            for (int off = 16; off; off >>= 1) p += __shfl_xor_sync(0xffffffffu, p, off);
            if (lane == 0) c[w] = p;
        }
    } else {
        int i = (blockIdx.x - 1) * blockDim.x + threadIdx.x;
        if (i < n) {
            int cc = cnt[i];
            la[i] = (cc > 0) ? (sumw[i] / (float)cc) : 0.0f;
        }
    }
}

// ---------------- aggregation (layers 0/1): half-warp per node -----------------
// 16-lane sub-warps: lane loads float4 (8 fp16 cols); 2 nodes in flight per warp.
// All shuffles use the per-segment mask (half-warps diverge in trip count).
__device__ __forceinline__ float lrelu(float a) { return a > 0.f ? a : 0.2f * a; }

__global__ void k_aggregate(const __half* __restrict__ xl, const float* __restrict__ asrc,
                            const float* __restrict__ adst, const int* __restrict__ ptr,
                            const int* __restrict__ csrc, const float* __restrict__ csw,
                            const float* __restrict__ la, const float* __restrict__ cvec,
                            int cidx, const float* __restrict__ bias,
                            __nv_bfloat16* __restrict__ obh, __nv_bfloat16* __restrict__ obl,
                            int n) {
    int hw = (blockIdx.x * blockDim.x + threadIdx.x) >> 4;
    int l = threadIdx.x & 15;
    uint32_t smask = 0xFFFFu << (threadIdx.x & 16);   // this half-warp's lanes only
    if (hw >= n) return;
    int v = hw;

    float c = cvec[cidx];
    float adv = adst[v];
    float a0 = lrelu(asrc[v] + adv + la[v] * c);
    int rs = ptr[v], re = ptr[v + 1];

    // pass A: exact max over self-loop + incoming edges
    float m = a0;
    for (int e = rs + l; e < re; e += 16)
        m = fmaxf(m, lrelu(asrc[csrc[e]] + adv + csw[e] * c));
#pragma unroll
    for (int o = 8; o; o >>= 1) m = fmaxf(m, __shfl_xor_sync(smask, m, o, 16));

    // pass B: fixed weights; lane covers cols [l*8, l*8+8) via one float4 (8 fp16)
    float w0 = __expf(a0 - m);
    float denp = (l == 0) ? w0 : 0.f;
    float acc[8];
    {
        float4 raw = ((const float4*)(xl + (size_t)v * 128))[l];
        const __half2* h2 = (const __half2*)&raw;
#pragma unroll
        for (int i = 0; i < 4; i++) {
            float2 f = __half22float2(h2[i]);
            acc[i * 2] = w0 * f.x; acc[i * 2 + 1] = w0 * f.y;
        }
    }
    for (int b = rs; b < re; b += 16) {
        int e = b + l;
        float w = 0.f;
        int sIdx = 0;
        if (e < re) {
            sIdx = csrc[e];
            w = __expf(lrelu(asrc[sIdx] + adv + csw[e] * c) - m);
        }
        denp += w;
        int cnt = min(16, re - b);
#pragma unroll 4
        for (int j = 0; j < cnt; j++) {
            float wj = __shfl_sync(smask, w, j, 16);
            int sj = __shfl_sync(smask, sIdx, j, 16);
            float4 raw = ((const float4*)(xl + (size_t)sj * 128))[l];
            const __half2* h2 = (const __half2*)&raw;
#pragma unroll
            for (int i = 0; i < 4; i++) {
                float2 f = __half22float2(h2[i]);
                acc[i * 2] += wj * f.x; acc[i * 2 + 1] += wj * f.y;
            }
        }
    }
#pragma unroll
    for (int o = 8; o; o >>= 1) denp += __shfl_xor_sync(smask, denp, o, 16);
    float inv = 1.0f / denp;

    float4 bv0 = ((const float4*)bias)[l * 2];
    float4 bv1 = ((const float4*)bias)[l * 2 + 1];
    float o_[8];
    o_[0] = fmaxf(acc[0] * inv + bv0.x, 0.f);
    o_[1] = fmaxf(acc[1] * inv + bv0.y, 0.f);
    o_[2] = fmaxf(acc[2] * inv + bv0.z, 0.f);
    o_[3] = fmaxf(acc[3] * inv + bv0.w, 0.f);
    o_[4] = fmaxf(acc[4] * inv + bv1.x, 0.f);
    o_[5] = fmaxf(acc[5] * inv + bv1.y, 0.f);
    o_[6] = fmaxf(acc[6] * inv + bv1.z, 0.f);
    o_[7] = fmaxf(acc[7] * inv + bv1.w, 0.f);

    __nv_bfloat162* ph = (__nv_bfloat162*)(obh + (size_t)v * 128) + l * 4;
    __nv_bfloat162* pl = (__nv_bfloat162*)(obl + (size_t)v * 128) + l * 4;
#pragma unroll
    for (int i = 0; i < 4; i++) {
        __nv_bfloat16 h0 = __float2bfloat16(o_[i * 2]);
        __nv_bfloat16 h1 = __float2bfloat16(o_[i * 2 + 1]);
        __nv_bfloat16 l0 = __float2bfloat16(o_[i * 2] - __bfloat162float(h0));
        __nv_bfloat16 l1 = __float2bfloat16(o_[i * 2 + 1] - __bfloat162float(h1));
        ph[i] = __nv_bfloat162(h0, h1);
        pl[i] = __nv_bfloat162(l0, l1);
    }
}

// ---------------- fused mu+logstd aggregation: half-warp per node --------------
// Lanes 0-7 cover mu cols (0-63), lanes 8-15 logstd cols (64-127), 8 cols/lane.
__global__ void k_aggdual(const __half* __restrict__ xl,
                          const float* __restrict__ asrcA, const float* __restrict__ adstA,
                          const float* __restrict__ asrcB, const float* __restrict__ adstB,
                          const int* __restrict__ ptr, const int* __restrict__ csrc,
                          const float* __restrict__ csw, const float* __restrict__ la,
                          const float* __restrict__ cvec,
                          const float* __restrict__ biasA, const float* __restrict__ biasB,
                          float* __restrict__ outA, float* __restrict__ outB, int n) {
    int hw = (blockIdx.x * blockDim.x + threadIdx.x) >> 4;
    int l = threadIdx.x & 15;
    uint32_t smask = 0xFFFFu << (threadIdx.x & 16);   // this half-warp's lanes only
    if (hw >= n) return;
    int v = hw;
    bool isA = l < 8;

    float c = cvec[2];
    float advA = adstA[v], advB = adstB[v];
    float lav = la[v];

    float a0A = lrelu(asrcA[v] + advA + lav * c);
    float a0B = lrelu(asrcB[v] + advB);
    int rs = ptr[v], re = ptr[v + 1];

    float mA = a0A, mB = a0B;
    for (int e = rs + l; e < re; e += 16) {
        int s = csrc[e];
        mA = fmaxf(mA, lrelu(asrcA[s] + advA + csw[e] * c));
        mB = fmaxf(mB, lrelu(asrcB[s] + advB));
    }
#pragma unroll
    for (int o = 8; o; o >>= 1) {
        mA = fmaxf(mA, __shfl_xor_sync(smask, mA, o, 16));
        mB = fmaxf(mB, __shfl_xor_sync(smask, mB, o, 16));
    }

    float w0A = __expf(a0A - mA), w0B = __expf(a0B - mB);
    float denA = (l == 0) ? w0A : 0.f;
    float denB = (l == 0) ? w0B : 0.f;
    float wsel0 = isA ? w0A : w0B;
    float acc[8];
    {
        float4 raw = ((const float4*)(xl + (size_t)v * 128))[l];
        const __half2* h2 = (const __half2*)&raw;
#pragma unroll
        for (int i = 0; i < 4; i++) {
            float2 f = __half22float2(h2[i]);
            acc[i * 2] = wsel0 * f.x; acc[i * 2 + 1] = wsel0 * f.y;
        }
    }
    for (int b = rs; b < re; b += 16) {
        int e = b + l;
        float wA = 0.f, wB = 0.f;
        int sIdx = 0;
        if (e < re) {
            sIdx = csrc[e];
            wA = __expf(lrelu(asrcA[sIdx] + advA + csw[e] * c) - mA);
            wB = __expf(lrelu(asrcB[sIdx] + advB) - mB);
        }
        denA += wA; denB += wB;
        int cnt = min(16, re - b);
#pragma unroll 4
        for (int j = 0; j < cnt; j++) {
            float wjA = __shfl_sync(smask, wA, j, 16);
            float wjB = __shfl_sync(smask, wB, j, 16);
            int sj = __shfl_sync(smask, sIdx, j, 16);
            float wj = isA ? wjA : wjB;
            float4 raw = ((const float4*)(xl + (size_t)sj * 128))[l];
            const __half2* h2 = (const __half2*)&raw;
#pragma unroll
            for (int i = 0; i < 4; i++) {
                float2 f = __half22float2(h2[i]);
                acc[i * 2] += wj * f.x; acc[i * 2 + 1] += wj * f.y;
            }
        }
    }
#pragma unroll
    for (int o = 8; o; o >>= 1) {
        denA += __shfl_xor_sync(smask, denA, o, 16);
        denB += __shfl_xor_sync(smask, denB, o, 16);
    }
    float inv = isA ? (1.0f / denA) : (1.0f / denB);

    if (isA) {
        float4 b0 = ((const float4*)biasA)[l * 2];
        float4 b1 = ((const float4*)biasA)[l * 2 + 1];
        float* dst = outA + (size_t)v * 64 + l * 8;
        ((float4*)dst)[0] = make_float4(acc[0] * inv + b0.x, acc[1] * inv + b0.y,
                                        acc[2] * inv + b0.z, acc[3] * inv + b0.w);
        ((float4*)dst)[1] = make_float4(acc[4] * inv + b1.x, acc[5] * inv + b1.y,
                                        acc[6] * inv + b1.z, acc[7] * inv + b1.w);
    } else {
        int lb = l - 8;
        float4 b0 = ((const float4*)biasB)[lb * 2];
        float4 b1 = ((const float4*)biasB)[lb * 2 + 1];
        float* dst = outB + (size_t)v * 64 + lb * 8;
        ((float4*)dst)[0] = make_float4(acc[0] * inv + b0.x, acc[1] * inv + b0.y,
                                        acc[2] * inv + b0.z, acc[3] * inv + b0.w);
        ((float4*)dst)[1] = make_float4(acc[4] * inv + b1.x, acc[5] * inv + b1.y,
                                        acc[6] * inv + b1.z, acc[7] * inv + b1.w);
    }
}

// ---------------- launch ------------------------------------------------------
extern "C" void kernel_launch(void* const* d_in, const int* in_sizes, int n_in,
                              void* d_out, int out_size) {
    const float* x      = (const float*)d_in[0];
    const void*  ei_raw = d_in[1];          // int32 or int64, probed at runtime
    const float* ew     = (const float*)d_in[2];
    const float *W0 = (const float*)d_in[3],  *as0 = (const float*)d_in[4],
                *ad0 = (const float*)d_in[5], *ae0 = (const float*)d_in[6],
                *We0 = (const float*)d_in[7], *b0  = (const float*)d_in[8];
    const float *W1 = (const float*)d_in[9],  *as1 = (const float*)d_in[10],
                *ad1 = (const float*)d_in[11], *ae1 = (const float*)d_in[12],
                *We1 = (const float*)d_in[13], *b1  = (const float*)d_in[14];
    const float *Wm = (const float*)d_in[15], *asm_ = (const float*)d_in[16],
                *adm = (const float*)d_in[17], *aem = (const float*)d_in[18],
                *Wem = (const float*)d_in[19], *bm  = (const float*)d_in[20];
    const float *Wl = (const float*)d_in[21], *asl = (const float*)d_in[22],
                *adl = (const float*)d_in[23], *bl  = (const float*)d_in[24];
    float* out = (float*)d_out;

    int *p_flag, *p_cnt, *p_fill, *p_ptr, *p_bsum, *p_csrc;
    float *p_csw, *p_sumw, *p_loop, *p_xl, *p_asrc, *p_adst, *p_asrc2, *p_adst2, *p_c;
    __nv_bfloat16 *p_bh, *p_bl, *p_wh, *p_wl;
    cudaGetSymbolAddress((void**)&p_flag, g_flag64);
    cudaGetSymbolAddress((void**)&p_cnt,  g_cnt);
    cudaGetSymbolAddress((void**)&p_fill, g_fill);
    cudaGetSymbolAddress((void**)&p_ptr,  g_ptr);
    cudaGetSymbolAddress((void**)&p_bsum, g_bsum);
    cudaGetSymbolAddress((void**)&p_csrc, g_csrc);
    cudaGetSymbolAddress((void**)&p_csw,  g_csw);
    cudaGetSymbolAddress((void**)&p_sumw, g_sumw);
    cudaGetSymbolAddress((void**)&p_loop, g_loop);
    cudaGetSymbolAddress((void**)&p_xl,   g_xl);
    cudaGetSymbolAddress((void**)&p_asrc, g_asrc);
    cudaGetSymbolAddress((void**)&p_adst, g_adst);
    cudaGetSymbolAddress((void**)&p_asrc2, g_asrc2);
    cudaGetSymbolAddress((void**)&p_adst2, g_adst2);
    cudaGetSymbolAddress((void**)&p_c,    g_c);
    cudaGetSymbolAddress((void**)&p_bh,   g_bh);
    cudaGetSymbolAddress((void**)&p_bl,   g_bl);
    cudaGetSymbolAddress((void**)&p_wh,   g_wh);
    cudaGetSymbolAddress((void**)&p_wl,   g_wl);
    __half* p_xlh = (__half*)p_xl;       // fp16 alias (all layers)

    const int sm128 = 2 * (128 * 272) + 4 * (128 * 272) + 2 * 128 * 4;
    cudaFuncSetAttribute(k_mma<false>, cudaFuncAttributeMaxDynamicSharedMemorySize, sm128);
    cudaFuncSetAttribute(k_mma<true>,  cudaFuncAttributeMaxDynamicSharedMemorySize, sm128);

    const int agg_blocks = (NN + 15) / 16;   // 16 half-warps/block, half-warp per node
    const int cx_blocks  = (NN * 128 / 4 + 255) / 256;

    // lazily-created side stream + fork/join events (host resources only;
    // created once, before any capture-relevant work of this call)
    static cudaStream_t s2 = 0;
    static cudaEvent_t ev0 = 0, ev1 = 0;
    if (!s2) {
        cudaStreamCreateWithFlags(&s2, cudaStreamNonBlocking);
        cudaEventCreateWithFlags(&ev0, cudaEventDisableTiming);
        cudaEventCreateWithFlags(&ev1, cudaEventDisableTiming);
    }

    // fork: CSR build on s2, GEMM prep on the main stream
    cudaEventRecord(ev0, 0);
    cudaStreamWaitEvent(s2, ev0, 0);

    // --- s2 branch: CSR build (independent of GEMM prep) ---
    k_zero<<<(NN + 255) / 256, 256, 0, s2>>>(p_cnt, p_fill, p_sumw, NN);
    k_probe<<<1, 256, 0, s2>>>(ei_raw, p_flag);
    k_hist<<<(NE + 511) / 512, 512, 0, s2>>>(ei_raw, p_flag, p_cnt, NE);
    k_scan1<<<NB_SCAN, SCAN_B, 0, s2>>>(p_cnt, p_ptr, p_bsum, NN);
    k_scan23<<<NB_SCAN, SCAN_B, 0, s2>>>(p_ptr, p_bsum, NN);
    k_scatter<<<(NE + 511) / 512, 512, 0, s2>>>(ei_raw, p_flag, ew, p_ptr, p_fill,
                                                p_csrc, p_csw, p_sumw, NE);
    k_misc<<<1 + (NN + 255) / 256, 256, 0, s2>>>(p_cnt, p_sumw, p_loop,
                                                 We0, ae0, We1, ae1, Wem, aem, p_c, NN);
    cudaEventRecord(ev1, s2);

    // --- main branch: weight/input conversion + layer-0 GEMM ---
    k_convw<<<(49152 + 255) / 256, 256>>>(W0, W1, Wm, Wl, p_wh, p_wl);
    k_convx<<<cx_blocks, 256>>>(x, p_bh, p_bl, NN * 128 / 4);
    k_mma<false><<<MMA_GRID, 256, sm128>>>(p_bh, p_bl, p_wh, p_wl, as0, ad0,
                                           nullptr, nullptr, p_xlh,
                                           p_asrc, p_adst, nullptr, nullptr, NN, NTILES);

    // join: aggregates need the CSR
    cudaStreamWaitEvent(0, ev1, 0);

    // layer 0 aggregate (fp16 gather) -> bf16 split
    k_aggregate<<<agg_blocks, 256>>>(p_xlh, p_asrc, p_adst, p_ptr, p_csrc, p_csw,
                                     p_loop, p_c, 0, b0, p_bh, p_bl, NN);
    // layer 1
    k_mma<false><<<MMA_GRID, 256, sm128>>>(p_bh, p_bl, p_wh + 16384, p_wl + 16384, as1, ad1,
                                           nullptr, nullptr, p_xlh,
                                           p_asrc, p_adst, nullptr, nullptr, NN, NTILES);
    k_aggregate<<<agg_blocks, 256>>>(p_xlh, p_asrc, p_adst, p_ptr, p_csrc, p_csw,
                                     p_loop, p_c, 1, b1, p_bh, p_bl, NN);
    // mu+logstd fused GEMM (combined weights at offset 32768) -> fp16 xl
    k_mma<true><<<MMA_GRID, 256, sm128>>>(p_bh, p_bl, p_wh + 32768, p_wl + 32768,
                                          asm_, adm, asl, adl, p_xlh,
                                          p_asrc, p_adst, p_asrc2, p_adst2, NN, NTILES);
    // fused mu+logstd aggregation (fp16 gather)
    k_aggdual<<<agg_blocks, 256>>>(p_xlh, p_asrc, p_adst, p_asrc2, p_adst2,
                                   p_ptr, p_csrc, p_csw, p_loop, p_c,
                                   bm, bl, out, out + (size_t)NN * 64, NN);
}

// round 17
// speedup vs baseline: 1.1261x; 1.0249x over previous
#include <cuda_runtime.h>
#include <cuda_bf16.h>
#include <cuda_fp16.h>
#include <cstdint>

// Problem constants (fixed by the dataset)
#define NN 100000
#define NE 1600000
#define SCAN_B 1024
#define NB_SCAN ((NN + SCAN_B - 1) / SCAN_B)   // 98
#define NTILES64 ((NN + 63) / 64)              // 1563
#define MMA_GRID 296

// ---------------- scratch (device globals; no allocation allowed) -------------
__device__ int   g_flag64;           // 1 if edge_index buffer is int64
__device__ int   g_cnt[NN];
__device__ int   g_fill[NN];
__device__ int   g_ptr[NN + 1];
__device__ int   g_bsum[128];
__device__ int   g_csrc[NE];
__device__ float g_csw[NE];
__device__ float g_sumw[NN];
__device__ float g_loop[NN];
__device__ float g_xl[(size_t)NN * 128];   // aliased as half (all layers gather fp16)
__device__ float g_asrc[NN];
__device__ float g_adst[NN];
__device__ float g_asrc2[NN];
__device__ float g_adst2[NN];
__device__ float g_c[4];
__device__ __nv_bfloat16 g_bh[(size_t)NN * 128];
__device__ __nv_bfloat16 g_bl[(size_t)NN * 128];
__device__ __nv_bfloat16 g_wh[49152];
__device__ __nv_bfloat16 g_wl[49152];

// ---------------- helpers -------------------------------------------------------
__device__ __forceinline__ uint32_t s2u(const void* p) {
    uint32_t a;
    asm("{ .reg .u64 t; cvta.to.shared.u64 t, %1; cvt.u32.u64 %0, t; }"
        : "=r"(a) : "l"(p));
    return a;
}
__device__ __forceinline__ void cp16(uint32_t saddr, const void* g, int sz) {
    asm volatile("cp.async.cg.shared.global [%0], [%1], 16, %2;"
                 :: "r"(saddr), "l"(g), "r"(sz));
}
__device__ __forceinline__ void cp_commit() {
    asm volatile("cp.async.commit_group;" ::: "memory");
}
__device__ __forceinline__ void cp_wait0() {
    asm volatile("cp.async.wait_group 0;" ::: "memory");
}
__device__ __forceinline__ void ldsm4(uint32_t* r, uint32_t addr) {
    asm volatile("ldmatrix.sync.aligned.m8n8.x4.shared.b16 {%0,%1,%2,%3}, [%4];"
                 : "=r"(r[0]), "=r"(r[1]), "=r"(r[2]), "=r"(r[3]) : "r"(addr));
}
__device__ __forceinline__ void mma16816(float* d, const uint32_t* a, const uint32_t* b) {
    asm volatile(
        "mma.sync.aligned.m16n8k16.row.col.f32.bf16.bf16.f32 "
        "{%0,%1,%2,%3}, {%4,%5,%6,%7}, {%8,%9}, {%0,%1,%2,%3};"
        : "+f"(d[0]), "+f"(d[1]), "+f"(d[2]), "+f"(d[3])
        : "r"(a[0]), "r"(a[1]), "r"(a[2]), "r"(a[3]), "r"(b[0]), "r"(b[1]));
}

// async-load a [ROWS x 128] bf16 K-major tile into smem, padded stride 272B
template <int ROWS, int NTHR>
__device__ __forceinline__ void load_tile(uint32_t sbase, const __nv_bfloat16* src,
                                          size_t row0, int nrows, int tid) {
#pragma unroll 4
    for (int c = tid; c < ROWS * 16; c += NTHR) {
        int row = c >> 4, kc = c & 15;
        uint32_t off = (uint32_t)row * 272 + kc * 16;
        size_t grow = (row < nrows) ? (row0 + row) : row0;
        cp16(sbase + off, src + grow * 128 + kc * 8, (row < nrows) ? 16 : 0);
    }
}

// ---------------- GEMM via mma.sync bf16x3 split --------------------------------
// M=64 tiles, 128 threads, single A buffer; 2 CTAs/SM provide the overlap.
// Y[n,128] = X[n,128] @ W[128,128]; 3 passes AhBh + AhBl + AlBh, fp32 accumulate.
// Y written fp16. DUAL: W = [Wm_t ; Wl_t]; mu dots -> asrc/adst, logstd -> *2.
template <bool DUAL>
__global__ void __launch_bounds__(128, 2)
k_mma(const __nv_bfloat16* __restrict__ Ah, const __nv_bfloat16* __restrict__ Al,
      const __nv_bfloat16* __restrict__ Bh, const __nv_bfloat16* __restrict__ Bl,
      const float* __restrict__ a_s, const float* __restrict__ a_d,
      const float* __restrict__ a_s2, const float* __restrict__ a_d2,
      __half* __restrict__ Yh,
      float* __restrict__ asrc, float* __restrict__ adst,
      float* __restrict__ asrc2, float* __restrict__ adst2,
      int n, int ntiles) {
    constexpr int NOUT = 128;
    constexpr int NT = 16;                     // n-tiles
    constexpr int WB = NOUT * 272;             // 34816 bytes per W split half
    constexpr int AB = 64 * 272;               // 17408 bytes per A split half
    extern __shared__ __align__(16) char smem[];
    char* sWh = smem;
    char* sWl = smem + WB;
    char* sA  = smem + 2 * WB;                 // single buf: Ah | Al
    float* sAtt = (float*)(smem + 2 * WB + 2 * AB);

    int tid = threadIdx.x, warp = tid >> 5, lane = tid & 31;

    if constexpr (DUAL) {
        for (int i = tid; i < 64; i += 128) {
            sAtt[i] = a_s[i]; sAtt[64 + i] = a_s2[i];
            sAtt[128 + i] = a_d[i]; sAtt[192 + i] = a_d2[i];
        }
    } else {
        for (int i = tid; i < NOUT; i += 128) { sAtt[i] = a_s[i]; sAtt[NOUT + i] = a_d[i]; }
    }

    uint32_t uWh = s2u(sWh), uWl = s2u(sWl), uA = s2u(sA);

    load_tile<NOUT, 128>(uWh, Bh, 0, NOUT, tid);
    load_tile<NOUT, 128>(uWl, Bl, 0, NOUT, tid);
    cp_commit();

    int mi = lane >> 3, l7 = lane & 7;
    uint32_t aoff = (uint32_t)(warp * 16 + ((mi & 1) << 3) + l7) * 272 + ((mi >> 1) << 3) * 2;
    uint32_t boff = (uint32_t)(((mi >> 1) << 3) + l7) * 272 + ((mi & 1) << 3) * 2;

    for (int t = blockIdx.x; t < ntiles; t += gridDim.x) {
        int nr = min(64, n - t * 64);
        load_tile<64, 128>(uA, Ah, (size_t)t * 64, nr, tid);
        load_tile<64, 128>(uA + AB, Al, (size_t)t * 64, nr, tid);
        cp_commit();
        cp_wait0();
        __syncthreads();

        float acc[NT][4];
#pragma unroll
        for (int j = 0; j < NT; j++)
#pragma unroll
            for (int q = 0; q < 4; q++) acc[j][q] = 0.f;

#pragma unroll
        for (int ks = 0; ks < 8; ks++) {
            uint32_t kb = ks * 32;
            uint32_t ah[4], al_[4];
            ldsm4(ah, uA + aoff + kb);
            ldsm4(al_, uA + AB + aoff + kb);
#pragma unroll
            for (int j = 0; j < NT; j += 2) {
                uint32_t bh[4], bl_[4];
                uint32_t bo = boff + (uint32_t)j * 8 * 272 + kb;
                ldsm4(bh, uWh + bo);
                ldsm4(bl_, uWl + bo);
                mma16816(acc[j],     ah,  bh);
                mma16816(acc[j + 1], ah,  bh + 2);
                mma16816(acc[j],     ah,  bl_);
                mma16816(acc[j + 1], ah,  bl_ + 2);
                mma16816(acc[j],     al_, bh);
                mma16816(acc[j + 1], al_, bh + 2);
            }
        }

        // epilogue
        int r0 = warp * 16 + (lane >> 2);
        int node0 = t * 64 + r0;
        int node1 = node0 + 8;
        bool v0 = node0 < n, v1 = node1 < n;
        float pa0 = 0.f, pd0 = 0.f, pa1 = 0.f, pd1 = 0.f;   // A-group (mu / full)
        float qa0 = 0.f, qd0 = 0.f, qa1 = 0.f, qd1 = 0.f;   // B-group (logstd, DUAL)
        int cb = (lane & 3) * 2;
#pragma unroll
        for (int j = 0; j < NT; j++) {
            int c = j * 8 + cb;
            float s0 = sAtt[c], s1 = sAtt[c + 1];
            float d0 = sAtt[NOUT + c], d1 = sAtt[NOUT + c + 1];
            if (DUAL && j >= NT / 2) {
                qa0 += acc[j][0] * s0 + acc[j][1] * s1;
                qd0 += acc[j][0] * d0 + acc[j][1] * d1;
                qa1 += acc[j][2] * s0 + acc[j][3] * s1;
                qd1 += acc[j][2] * d0 + acc[j][3] * d1;
            } else {
                pa0 += acc[j][0] * s0 + acc[j][1] * s1;
                pd0 += acc[j][0] * d0 + acc[j][1] * d1;
                pa1 += acc[j][2] * s0 + acc[j][3] * s1;
                pd1 += acc[j][2] * d0 + acc[j][3] * d1;
            }
            if (v0) *(__half2*)(Yh + (size_t)node0 * NOUT + c) = __floats2half2_rn(acc[j][0], acc[j][1]);
            if (v1) *(__half2*)(Yh + (size_t)node1 * NOUT + c) = __floats2half2_rn(acc[j][2], acc[j][3]);
        }
#pragma unroll
        for (int o = 1; o <= 2; o <<= 1) {
            pa0 += __shfl_xor_sync(0xffffffffu, pa0, o);
            pd0 += __shfl_xor_sync(0xffffffffu, pd0, o);
            pa1 += __shfl_xor_sync(0xffffffffu, pa1, o);
            pd1 += __shfl_xor_sync(0xffffffffu, pd1, o);
            if (DUAL) {
                qa0 += __shfl_xor_sync(0xffffffffu, qa0, o);
                qd0 += __shfl_xor_sync(0xffffffffu, qd0, o);
                qa1 += __shfl_xor_sync(0xffffffffu, qa1, o);
                qd1 += __shfl_xor_sync(0xffffffffu, qd1, o);
            }
        }
        if ((lane & 3) == 0) {
            if (v0) {
                asrc[node0] = pa0; adst[node0] = pd0;
                if (DUAL) { asrc2[node0] = qa0; adst2[node0] = qd0; }
            }
            if (v1) {
                asrc[node1] = pa1; adst[node1] = pd1;
                if (DUAL) { asrc2[node1] = qa1; adst2[node1] = qd1; }
            }
        }
        __syncthreads();
    }
}

// ---------------- fp32 -> bf16 hi/lo split -------------------------------------
__global__ void k_convx(const float* __restrict__ s, __nv_bfloat16* __restrict__ bh,
                        __nv_bfloat16* __restrict__ bl, int n4) {
    int i = blockIdx.x * blockDim.x + threadIdx.x;
    if (i >= n4) return;
    float4 v = ((const float4*)s)[i];
    __nv_bfloat16 h0 = __float2bfloat16(v.x), h1 = __float2bfloat16(v.y);
    __nv_bfloat16 h2 = __float2bfloat16(v.z), h3 = __float2bfloat16(v.w);
    __nv_bfloat16 l0 = __float2bfloat16(v.x - __bfloat162float(h0));
    __nv_bfloat16 l1 = __float2bfloat16(v.y - __bfloat162float(h1));
    __nv_bfloat16 l2 = __float2bfloat16(v.z - __bfloat162float(h2));
    __nv_bfloat16 l3 = __float2bfloat16(v.w - __bfloat162float(h3));
    ((__nv_bfloat162*)bh)[i * 2]     = __nv_bfloat162(h0, h1);
    ((__nv_bfloat162*)bh)[i * 2 + 1] = __nv_bfloat162(h2, h3);
    ((__nv_bfloat162*)bl)[i * 2]     = __nv_bfloat162(l0, l1);
    ((__nv_bfloat162*)bl)[i * 2 + 1] = __nv_bfloat162(l2, l3);
}

// transpose + split all 4 weight matrices into wt[n*128+k] hi/lo
__global__ void k_convw(const float* __restrict__ W0, const float* __restrict__ W1,
                        const float* __restrict__ Wm, const float* __restrict__ Wl,
                        __nv_bfloat16* __restrict__ wh, __nv_bfloat16* __restrict__ wl_) {
    int i = blockIdx.x * blockDim.x + threadIdx.x;
    if (i >= 49152) return;
    float v;
    if (i < 16384)      { int j = i;         int nn = j >> 7, k = j & 127; v = W0[k * 128 + nn]; }
    else if (i < 32768) { int j = i - 16384; int nn = j >> 7, k = j & 127; v = W1[k * 128 + nn]; }
    else if (i < 40960) { int j = i - 32768; int nn = j >> 7, k = j & 127; v = Wm[k * 64 + nn]; }
    else                { int j = i - 40960; int nn = j >> 7, k = j & 127; v = Wl[k * 64 + nn]; }
    __nv_bfloat16 h = __float2bfloat16(v);
    wh[i] = h;
    wl_[i] = __float2bfloat16(v - __bfloat162float(h));
}

// ---------------- zero scratch -------------------------------------------------
__global__ void k_zero(int* __restrict__ cnt, int* __restrict__ fill,
                       float* __restrict__ sumw, int n) {
    int i = blockIdx.x * blockDim.x + threadIdx.x;
    if (i < n) { cnt[i] = 0; fill[i] = 0; sumw[i] = 0.f; }
}

// ---------------- dtype probe --------------------------------------------------
__global__ void k_probe(const void* __restrict__ ei_raw, int* __restrict__ flag) {
    __shared__ int bad;
    if (threadIdx.x == 0) bad = 0;
    __syncthreads();
    const long long* p = (const long long*)ei_raw;
    for (int i = threadIdx.x; i < 4096; i += blockDim.x) {
        long long v = p[i];
        if (v < 0 || v >= (long long)NN) bad = 1;
    }
    __syncthreads();
    if (threadIdx.x == 0) *flag = bad ? 0 : 1;
}

// histogram of destination degrees (reads edge_index directly)
__global__ void k_hist(const void* __restrict__ ei_raw, const int* __restrict__ flag,
                       int* __restrict__ cnt, int E) {
    int e = blockIdx.x * blockDim.x + threadIdx.x;
    if (e >= E) return;
    int d;
    if (__ldg(flag)) d = (int)((const long long*)ei_raw)[E + e];
    else             d = ((const int*)ei_raw)[E + e];
    atomicAdd(&cnt[d], 1);
}

// ---------------- CSR build ---------------------------------------------------
__global__ void k_scan1(const int* __restrict__ cnt, int* __restrict__ ptr,
                        int* __restrict__ bsum, int n) {
    __shared__ int sm[SCAN_B];
    int i = blockIdx.x * SCAN_B + threadIdx.x;
    int v = (i < n) ? cnt[i] : 0;
    sm[threadIdx.x] = v;
    __syncthreads();
    for (int off = 1; off < SCAN_B; off <<= 1) {
        int t = (threadIdx.x >= off) ? sm[threadIdx.x - off] : 0;
        __syncthreads();
        sm[threadIdx.x] += t;
        __syncthreads();
    }
    if (i < n) ptr[i + 1] = sm[threadIdx.x];
    if (threadIdx.x == SCAN_B - 1) bsum[blockIdx.x] = sm[SCAN_B - 1];
    if (i == 0) ptr[0] = 0;
}

__global__ void k_scan23(int* __restrict__ ptr, const int* __restrict__ bsum, int n) {
    __shared__ int sm[128];
    int t = threadIdx.x;
    if (t < 128) sm[t] = (t < (int)blockIdx.x && t < NB_SCAN) ? bsum[t] : 0;
    __syncthreads();
    for (int off = 64; off; off >>= 1) {
        if (t < off) sm[t] += sm[t + off];
        __syncthreads();
    }
    int offs = sm[0];
    int i = blockIdx.x * SCAN_B + t;
    if (i < n) ptr[i + 1] += offs;
}

__global__ void k_scatter(const void* __restrict__ ei_raw, const int* __restrict__ flag,
                          const float* __restrict__ ew,
                          const int* __restrict__ ptr, int* __restrict__ fill,
                          int* __restrict__ csrc, float* __restrict__ csw,
                          float* __restrict__ sumw, int E) {
    int e = blockIdx.x * blockDim.x + threadIdx.x;
    if (e >= E) return;
    int s, d;
    if (__ldg(flag)) {
        const long long* p = (const long long*)ei_raw;
        s = (int)p[e]; d = (int)p[E + e];
    } else {
        const int* p = (const int*)ei_raw;
        s = p[e]; d = p[E + e];
    }
    float w = ew[e];
    int pos = ptr[d] + atomicAdd(&fill[d], 1);
    csrc[pos] = s;
    csw[pos] = w;
    atomicAdd(&sumw[d], w);
}

// fused: 3 edge-attention dots (block 0) + self-loop attr (blocks 1..)
__global__ void k_misc(const int* __restrict__ cnt, const float* __restrict__ sumw,
                       float* __restrict__ la,
                       const float* __restrict__ We0, const float* __restrict__ ae0,
                       const float* __restrict__ We1, const float* __restrict__ ae1,
                       const float* __restrict__ Wem, const float* __restrict__ aem,
                       float* __restrict__ c, int n) {
    if (blockIdx.x == 0) {
        int w = threadIdx.x >> 5, lane = threadIdx.x & 31;
        if (w < 3) {
            const float* A = (w == 0) ? We0 : ((w == 1) ? We1 : Wem);
            const float* B = (w == 0) ? ae0 : ((w == 1) ? ae1 : aem);
            int len = (w == 2) ? 64 : 128;
            float p = 0.f;
            for (int i = lane; i < len; i += 32) p += A[i] * B[i];
#pragma unroll
            for (int off = 16; off; off >>= 1) p += __shfl_xor_sync(0xffffffffu, p, off);
            if (lane == 0) c[w] = p;
        }
    } else {
        int i = (blockIdx.x - 1) * blockDim.x + threadIdx.x;
        if (i < n) {
            int cc = cnt[i];
            la[i] = (cc > 0) ? (sumw[i] / (float)cc) : 0.0f;
        }
    }
}

// ---------------- aggregation (layers 0/1): half-warp per node -----------------
__device__ __forceinline__ float lrelu(float a) { return a > 0.f ? a : 0.2f * a; }

__global__ void k_aggregate(const __half* __restrict__ xl, const float* __restrict__ asrc,
                            const float* __restrict__ adst, const int* __restrict__ ptr,
                            const int* __restrict__ csrc, const float* __restrict__ csw,
                            const float* __restrict__ la, const float* __restrict__ cvec,
                            int cidx, const float* __restrict__ bias,
                            __nv_bfloat16* __restrict__ obh, __nv_bfloat16* __restrict__ obl,
                            int n) {
    int hw = (blockIdx.x * blockDim.x + threadIdx.x) >> 4;
    int l = threadIdx.x & 15;
    uint32_t smask = 0xFFFFu << (threadIdx.x & 16);   // this half-warp's lanes only
    if (hw >= n) return;
    int v = hw;

    float c = cvec[cidx];
    float adv = adst[v];
    float a0 = lrelu(asrc[v] + adv + la[v] * c);
    int rs = ptr[v], re = ptr[v + 1];

    float m = a0;
    for (int e = rs + l; e < re; e += 16)
        m = fmaxf(m, lrelu(asrc[csrc[e]] + adv + csw[e] * c));
#pragma unroll
    for (int o = 8; o; o >>= 1) m = fmaxf(m, __shfl_xor_sync(smask, m, o, 16));

    float w0 = __expf(a0 - m);
    float denp = (l == 0) ? w0 : 0.f;
    float acc[8];
    {
        float4 raw = ((const float4*)(xl + (size_t)v * 128))[l];
        const __half2* h2 = (const __half2*)&raw;
#pragma unroll
        for (int i = 0; i < 4; i++) {
            float2 f = __half22float2(h2[i]);
            acc[i * 2] = w0 * f.x; acc[i * 2 + 1] = w0 * f.y;
        }
    }
    for (int b = rs; b < re; b += 16) {
        int e = b + l;
        float w = 0.f;
        int sIdx = 0;
        if (e < re) {
            sIdx = csrc[e];
            w = __expf(lrelu(asrc[sIdx] + adv + csw[e] * c) - m);
        }
        denp += w;
        int cnt = min(16, re - b);
#pragma unroll 4
        for (int j = 0; j < cnt; j++) {
            float wj = __shfl_sync(smask, w, j, 16);
            int sj = __shfl_sync(smask, sIdx, j, 16);
            float4 raw = ((const float4*)(xl + (size_t)sj * 128))[l];
            const __half2* h2 = (const __half2*)&raw;
#pragma unroll
            for (int i = 0; i < 4; i++) {
                float2 f = __half22float2(h2[i]);
                acc[i * 2] += wj * f.x; acc[i * 2 + 1] += wj * f.y;
            }
        }
    }
#pragma unroll
    for (int o = 8; o; o >>= 1) denp += __shfl_xor_sync(smask, denp, o, 16);
    float inv = 1.0f / denp;

    float4 bv0 = ((const float4*)bias)[l * 2];
    float4 bv1 = ((const float4*)bias)[l * 2 + 1];
    float o_[8];
    o_[0] = fmaxf(acc[0] * inv + bv0.x, 0.f);
    o_[1] = fmaxf(acc[1] * inv + bv0.y, 0.f);
    o_[2] = fmaxf(acc[2] * inv + bv0.z, 0.f);
    o_[3] = fmaxf(acc[3] * inv + bv0.w, 0.f);
    o_[4] = fmaxf(acc[4] * inv + bv1.x, 0.f);
    o_[5] = fmaxf(acc[5] * inv + bv1.y, 0.f);
    o_[6] = fmaxf(acc[6] * inv + bv1.z, 0.f);
    o_[7] = fmaxf(acc[7] * inv + bv1.w, 0.f);

    __nv_bfloat162* ph = (__nv_bfloat162*)(obh + (size_t)v * 128) + l * 4;
    __nv_bfloat162* pl = (__nv_bfloat162*)(obl + (size_t)v * 128) + l * 4;
#pragma unroll
    for (int i = 0; i < 4; i++) {
        __nv_bfloat16 h0 = __float2bfloat16(o_[i * 2]);
        __nv_bfloat16 h1 = __float2bfloat16(o_[i * 2 + 1]);
        __nv_bfloat16 l0 = __float2bfloat16(o_[i * 2] - __bfloat162float(h0));
        __nv_bfloat16 l1 = __float2bfloat16(o_[i * 2 + 1] - __bfloat162float(h1));
        ph[i] = __nv_bfloat162(h0, h1);
        pl[i] = __nv_bfloat162(l0, l1);
    }
}

// ---------------- fused mu+logstd aggregation: half-warp per node --------------
__global__ void k_aggdual(const __half* __restrict__ xl,
                          const float* __restrict__ asrcA, const float* __restrict__ adstA,
                          const float* __restrict__ asrcB, const float* __restrict__ adstB,
                          const int* __restrict__ ptr, const int* __restrict__ csrc,
                          const float* __restrict__ csw, const float* __restrict__ la,
                          const float* __restrict__ cvec,
                          const float* __restrict__ biasA, const float* __restrict__ biasB,
                          float* __restrict__ outA, float* __restrict__ outB, int n) {
    int hw = (blockIdx.x * blockDim.x + threadIdx.x) >> 4;
    int l = threadIdx.x & 15;
    uint32_t smask = 0xFFFFu << (threadIdx.x & 16);
    if (hw >= n) return;
    int v = hw;
    bool isA = l < 8;

    float c = cvec[2];
    float advA = adstA[v], advB = adstB[v];
    float lav = la[v];

    float a0A = lrelu(asrcA[v] + advA + lav * c);
    float a0B = lrelu(asrcB[v] + advB);
    int rs = ptr[v], re = ptr[v + 1];

    float mA = a0A, mB = a0B;
    for (int e = rs + l; e < re; e += 16) {
        int s = csrc[e];
        mA = fmaxf(mA, lrelu(asrcA[s] + advA + csw[e] * c));
        mB = fmaxf(mB, lrelu(asrcB[s] + advB));
    }
#pragma unroll
    for (int o = 8; o; o >>= 1) {
        mA = fmaxf(mA, __shfl_xor_sync(smask, mA, o, 16));
        mB = fmaxf(mB, __shfl_xor_sync(smask, mB, o, 16));
    }

    float w0A = __expf(a0A - mA), w0B = __expf(a0B - mB);
    float denA = (l == 0) ? w0A : 0.f;
    float denB = (l == 0) ? w0B : 0.f;
    float wsel0 = isA ? w0A : w0B;
    float acc[8];
    {
        float4 raw = ((const float4*)(xl + (size_t)v * 128))[l];
        const __half2* h2 = (const __half2*)&raw;
#pragma unroll
        for (int i = 0; i < 4; i++) {
            float2 f = __half22float2(h2[i]);
            acc[i * 2] = wsel0 * f.x; acc[i * 2 + 1] = wsel0 * f.y;
        }
    }
    for (int b = rs; b < re; b += 16) {
        int e = b + l;
        float wA = 0.f, wB = 0.f;
        int sIdx = 0;
        if (e < re) {
            sIdx = csrc[e];
            wA = __expf(lrelu(asrcA[sIdx] + advA + csw[e] * c) - mA);
            wB = __expf(lrelu(asrcB[sIdx] + advB) - mB);
        }
        denA += wA; denB += wB;
        int cnt = min(16, re - b);
#pragma unroll 4
        for (int j = 0; j < cnt; j++) {
            float wjA = __shfl_sync(smask, wA, j, 16);
            float wjB = __shfl_sync(smask, wB, j, 16);
            int sj = __shfl_sync(smask, sIdx, j, 16);
            float wj = isA ? wjA : wjB;
            float4 raw = ((const float4*)(xl + (size_t)sj * 128))[l];
            const __half2* h2 = (const __half2*)&raw;
#pragma unroll
            for (int i = 0; i < 4; i++) {
                float2 f = __half22float2(h2[i]);
                acc[i * 2] += wj * f.x; acc[i * 2 + 1] += wj * f.y;
            }
        }
    }
#pragma unroll
    for (int o = 8; o; o >>= 1) {
        denA += __shfl_xor_sync(smask, denA, o, 16);
        denB += __shfl_xor_sync(smask, denB, o, 16);
    }
    float inv = isA ? (1.0f / denA) : (1.0f / denB);

    if (isA) {
        float4 b0 = ((const float4*)biasA)[l * 2];
        float4 b1 = ((const float4*)biasA)[l * 2 + 1];
        float* dst = outA + (size_t)v * 64 + l * 8;
        ((float4*)dst)[0] = make_float4(acc[0] * inv + b0.x, acc[1] * inv + b0.y,
                                        acc[2] * inv + b0.z, acc[3] * inv + b0.w);
        ((float4*)dst)[1] = make_float4(acc[4] * inv + b1.x, acc[5] * inv + b1.y,
                                        acc[6] * inv + b1.z, acc[7] * inv + b1.w);
    } else {
        int lb = l - 8;
        float4 b0 = ((const float4*)biasB)[lb * 2];
        float4 b1 = ((const float4*)biasB)[lb * 2 + 1];
        float* dst = outB + (size_t)v * 64 + lb * 8;
        ((float4*)dst)[0] = make_float4(acc[0] * inv + b0.x, acc[1] * inv + b0.y,
                                        acc[2] * inv + b0.z, acc[3] * inv + b0.w);
        ((float4*)dst)[1] = make_float4(acc[4] * inv + b1.x, acc[5] * inv + b1.y,
                                        acc[6] * inv + b1.z, acc[7] * inv + b1.w);
    }
}

// ---------------- launch ------------------------------------------------------
extern "C" void kernel_launch(void* const* d_in, const int* in_sizes, int n_in,
                              void* d_out, int out_size) {
    const float* x      = (const float*)d_in[0];
    const void*  ei_raw = d_in[1];          // int32 or int64, probed at runtime
    const float* ew     = (const float*)d_in[2];
    const float *W0 = (const float*)d_in[3],  *as0 = (const float*)d_in[4],
                *ad0 = (const float*)d_in[5], *ae0 = (const float*)d_in[6],
                *We0 = (const float*)d_in[7], *b0  = (const float*)d_in[8];
    const float *W1 = (const float*)d_in[9],  *as1 = (const float*)d_in[10],
                *ad1 = (const float*)d_in[11], *ae1 = (const float*)d_in[12],
                *We1 = (const float*)d_in[13], *b1  = (const float*)d_in[14];
    const float *Wm = (const float*)d_in[15], *asm_ = (const float*)d_in[16],
                *adm = (const float*)d_in[17], *aem = (const float*)d_in[18],
                *Wem = (const float*)d_in[19], *bm  = (const float*)d_in[20];
    const float *Wl = (const float*)d_in[21], *asl = (const float*)d_in[22],
                *adl = (const float*)d_in[23], *bl  = (const float*)d_in[24];
    float* out = (float*)d_out;

    int *p_flag, *p_cnt, *p_fill, *p_ptr, *p_bsum, *p_csrc;
    float *p_csw, *p_sumw, *p_loop, *p_xl, *p_asrc, *p_adst, *p_asrc2, *p_adst2, *p_c;
    __nv_bfloat16 *p_bh, *p_bl, *p_wh, *p_wl;
    cudaGetSymbolAddress((void**)&p_flag, g_flag64);
    cudaGetSymbolAddress((void**)&p_cnt,  g_cnt);
    cudaGetSymbolAddress((void**)&p_fill, g_fill);
    cudaGetSymbolAddress((void**)&p_ptr,  g_ptr);
    cudaGetSymbolAddress((void**)&p_bsum, g_bsum);
    cudaGetSymbolAddress((void**)&p_csrc, g_csrc);
    cudaGetSymbolAddress((void**)&p_csw,  g_csw);
    cudaGetSymbolAddress((void**)&p_sumw, g_sumw);
    cudaGetSymbolAddress((void**)&p_loop, g_loop);
    cudaGetSymbolAddress((void**)&p_xl,   g_xl);
    cudaGetSymbolAddress((void**)&p_asrc, g_asrc);
    cudaGetSymbolAddress((void**)&p_adst, g_adst);
    cudaGetSymbolAddress((void**)&p_asrc2, g_asrc2);
    cudaGetSymbolAddress((void**)&p_adst2, g_adst2);
    cudaGetSymbolAddress((void**)&p_c,    g_c);
    cudaGetSymbolAddress((void**)&p_bh,   g_bh);
    cudaGetSymbolAddress((void**)&p_bl,   g_bl);
    cudaGetSymbolAddress((void**)&p_wh,   g_wh);
    cudaGetSymbolAddress((void**)&p_wl,   g_wl);
    __half* p_xlh = (__half*)p_xl;       // fp16 alias (all layers)

    // smem: 2 W halves + 1 A buf (2 halves, 64 rows) + attention vecs
    const int smA = 2 * (128 * 272) + 2 * (64 * 272) + 2 * 128 * 4;   // ~106 KB
    cudaFuncSetAttribute(k_mma<false>, cudaFuncAttributeMaxDynamicSharedMemorySize, smA);
    cudaFuncSetAttribute(k_mma<true>,  cudaFuncAttributeMaxDynamicSharedMemorySize, smA);

    const int agg_blocks = (NN + 15) / 16;   // 16 half-warps/block, half-warp per node
    const int cx_blocks  = (NN * 128 / 4 + 255) / 256;

    // 1: weight transpose + bf16 split
    k_convw<<<(49152 + 255) / 256, 256>>>(W0, W1, Wm, Wl, p_wh, p_wl);
    // 2: split input x
    k_convx<<<cx_blocks, 256>>>(x, p_bh, p_bl, NN * 128 / 4);
    // 3: zero scratch
    k_zero<<<(NN + 255) / 256, 256>>>(p_cnt, p_fill, p_sumw, NN);
    // 4: layer-0 GEMM (profiled slot) -> fp16 xl
    k_mma<false><<<MMA_GRID, 128, smA>>>(p_bh, p_bl, p_wh, p_wl, as0, ad0,
                                         nullptr, nullptr, p_xlh,
                                         p_asrc, p_adst, nullptr, nullptr, NN, NTILES64);
    // 5-9: CSR build
    k_probe<<<1, 256>>>(ei_raw, p_flag);
    k_hist<<<(NE + 511) / 512, 512>>>(ei_raw, p_flag, p_cnt, NE);
    k_scan1<<<NB_SCAN, SCAN_B>>>(p_cnt, p_ptr, p_bsum, NN);
    k_scan23<<<NB_SCAN, SCAN_B>>>(p_ptr, p_bsum, NN);
    k_scatter<<<(NE + 511) / 512, 512>>>(ei_raw, p_flag, ew, p_ptr, p_fill,
                                         p_csrc, p_csw, p_sumw, NE);
    // 10: edge-attention scalars + self-loop attrs
    k_misc<<<1 + (NN + 255) / 256, 256>>>(p_cnt, p_sumw, p_loop,
                                          We0, ae0, We1, ae1, Wem, aem, p_c, NN);

    // layer 0 aggregate (fp16 gather) -> bf16 split
    k_aggregate<<<agg_blocks, 256>>>(p_xlh, p_asrc, p_adst, p_ptr, p_csrc, p_csw,
                                     p_loop, p_c, 0, b0, p_bh, p_bl, NN);
    // layer 1
    k_mma<false><<<MMA_GRID, 128, smA>>>(p_bh, p_bl, p_wh + 16384, p_wl + 16384, as1, ad1,
                                         nullptr, nullptr, p_xlh,
                                         p_asrc, p_adst, nullptr, nullptr, NN, NTILES64);
    k_aggregate<<<agg_blocks, 256>>>(p_xlh, p_asrc, p_adst, p_ptr, p_csrc, p_csw,
                                     p_loop, p_c, 1, b1, p_bh, p_bl, NN);
    // mu+logstd fused GEMM (combined weights at offset 32768) -> fp16 xl
    k_mma<true><<<MMA_GRID, 128, smA>>>(p_bh, p_bl, p_wh + 32768, p_wl + 32768,
                                        asm_, adm, asl, adl, p_xlh,
                                        p_asrc, p_adst, p_asrc2, p_adst2, NN, NTILES64);
    // fused mu+logstd aggregation (fp16 gather)
    k_aggdual<<<agg_blocks, 256>>>(p_xlh, p_asrc, p_adst, p_asrc2, p_adst2,
                                   p_ptr, p_csrc, p_csw, p_loop, p_c,
                                   bm, bl, out, out + (size_t)NN * 64, NN);
}